// round 4
// baseline (speedup 1.0000x reference)
#include <cuda_runtime.h>
#include <cuda_bf16.h>
#include <math.h>
#include <stdint.h>

#define ATTN_SCALE 0.17677669529663687f  // 32^-0.5

__device__ __forceinline__ uint32_t smem_u32(const void* p) {
    uint32_t a;
    asm("{ .reg .u64 t; cvta.to.shared.u64 t, %1; cvt.u32.u64 %0, t; }" : "=r"(a) : "l"(p));
    return a;
}
__device__ __forceinline__ void cp16(uint32_t s, const void* g) {
    asm volatile("cp.async.cg.shared.global [%0], [%1], 16;" :: "r"(s), "l"(g));
}
__device__ __forceinline__ void cp_commit() { asm volatile("cp.async.commit_group;"); }
__device__ __forceinline__ void cp_wait3() { asm volatile("cp.async.wait_group 3;"); }
__device__ __forceinline__ void ldsm4(uint32_t r[4], uint32_t addr) {
    asm volatile("ldmatrix.sync.aligned.m8n8.x4.shared.b16 {%0,%1,%2,%3}, [%4];"
                 : "=r"(r[0]), "=r"(r[1]), "=r"(r[2]), "=r"(r[3]) : "r"(addr));
}
__device__ __forceinline__ void mma16816(float c[4], const uint32_t a[4], uint32_t b0,
                                         uint32_t b1) {
    asm volatile(
        "mma.sync.aligned.m16n8k16.row.col.f32.bf16.bf16.f32 "
        "{%0,%1,%2,%3}, {%4,%5,%6,%7}, {%8,%9}, {%0,%1,%2,%3};"
        : "+f"(c[0]), "+f"(c[1]), "+f"(c[2]), "+f"(c[3])
        : "r"(a[0]), "r"(a[1]), "r"(a[2]), "r"(a[3]), "r"(b0), "r"(b1));
}
__device__ __forceinline__ void split_bf16(float v, __nv_bfloat16& hi, __nv_bfloat16& lo) {
    hi = __float2bfloat16(v);
    lo = __float2bfloat16(v - __bfloat162float(hi));
}

// =================== device scratch ===================
__device__ __nv_bfloat16 g_Xncat[4096 * 768];
__device__ __nv_bfloat16 g_Wkvcat[1024 * 768];
__device__ float g_bcat[1024];
__device__ float g_KV[4096 * 1024];
__device__ float g_x[4096 * 256];
__device__ __nv_bfloat16 g_tcat[4096 * 768];
__device__ float g_q[4096 * 256];
__device__ __nv_bfloat16 g_acat[4096 * 768];
__device__ float g_z1[4096 * 256];
__device__ float g_z2[4096 * 256];
__device__ __nv_bfloat16 g_z2cat[4096 * 768];
__device__ __nv_bfloat16 g_hcat[4096 * 1536];
__device__ float g_z3[4096 * 256];
__device__ __nv_bfloat16 g_Wq2[2 * 256 * 768];
__device__ __nv_bfloat16 g_Wp2[2 * 256 * 768];
__device__ __nv_bfloat16 g_Wm1c[2 * 512 * 768];
__device__ __nv_bfloat16 g_Wm2c[2 * 256 * 1536];
__device__ float g_inv[4096];
__device__ int g_jL[4096], g_jR[4096];

// =================== small prep kernels ===================
__global__ void idx_kernel(const float* __restrict__ u, int* __restrict__ jL,
                           int* __restrict__ jR) {
    int m = blockIdx.x * 256 + threadIdx.x;
    float uf = floorf(u[m]);
    jL[m] = (int)fminf(fmaxf(uf, 0.f), 127.f);
    jR[m] = (int)fminf(fmaxf(uf + 1.f, 0.f), 127.f);
}

// column-LN of grd_x (C=256 rows, 4096 cols) -> cat rows [hi|hi|lo], coalesced
__global__ __launch_bounds__(256) void colnorm_kernel(const float* __restrict__ gx,
                                                      __nv_bfloat16* __restrict__ cat) {
    __shared__ float tile[256][33];
    __shared__ float ps[8][32], pq[8][32];
    __shared__ float cmu[32], crs[32];
    int tx = threadIdx.x & 31, ty = threadIdx.x >> 5;
    int j0 = blockIdx.x * 32;
    float s = 0.f, q = 0.f;
#pragma unroll
    for (int t = 0; t < 32; t++) {
        int c = t * 8 + ty;
        float v = gx[(size_t)c * 4096 + j0 + tx];
        tile[c][tx] = v;
        s += v; q += v * v;
    }
    ps[ty][tx] = s; pq[ty][tx] = q;
    __syncthreads();
    if (ty == 0) {
        float ss = 0.f, qq = 0.f;
#pragma unroll
        for (int r = 0; r < 8; r++) { ss += ps[r][tx]; qq += pq[r][tx]; }
        float mu = ss * (1.f / 256.f);
        cmu[tx] = mu;
        crs[tx] = rsqrtf(qq * (1.f / 256.f) - mu * mu + 1e-5f);
    }
    __syncthreads();
    int lane = tx, w = ty;
#pragma unroll
    for (int r = 0; r < 4; r++) {
        int jj = w * 4 + r;
        float mu = cmu[jj], rs = crs[jj];
        size_t rb = (size_t)(j0 + jj) * 768 + lane * 8;
        __nv_bfloat16 h[8], l[8];
#pragma unroll
        for (int e = 0; e < 8; e++) {
            float v = (tile[lane * 8 + e][jj] - mu) * rs;
            split_bf16(v, h[e], l[e]);
        }
        *(uint4*)(cat + rb) = *(uint4*)h;
        *(uint4*)(cat + rb + 256) = *(uint4*)h;
        *(uint4*)(cat + rb + 512) = *(uint4*)l;
    }
}

// KV weights -> cat rows [hi|lo|hi] with LN weight folded; tile transpose, coalesced
__global__ void fold_w_kernel(const float* __restrict__ Wk, const float* __restrict__ Wv,
                              const float* __restrict__ lnkw, const float* __restrict__ lnvw,
                              __nv_bfloat16* __restrict__ cat) {
    __shared__ float t[32][33];
    int seg = blockIdx.z;          // 0..3 -> [k0,v0,k1,v1]
    int i = seg >> 1, isv = seg & 1;
    const float* W = (isv ? Wv : Wk) + i * 65536;
    const float* lw = (isv ? lnvw : lnkw) + i * 256;
    int c0 = blockIdx.x * 32, o0 = blockIdx.y * 32;
    int tx = threadIdx.x, ty = threadIdx.y;
#pragma unroll
    for (int s = 0; s < 4; s++) {
        int c = c0 + ty + s * 8;
        t[ty + s * 8][tx] = W[(size_t)c * 256 + o0 + tx] * lw[c];
    }
    __syncthreads();
#pragma unroll
    for (int s = 0; s < 4; s++) {
        int o = o0 + ty + s * 8;
        float v = t[tx][ty + s * 8];
        __nv_bfloat16 hi, lo;
        split_bf16(v, hi, lo);
        size_t rb = (size_t)(seg * 256 + o) * 768;
        cat[rb + c0 + tx] = hi;
        cat[rb + 256 + c0 + tx] = lo;
        cat[rb + 512 + c0 + tx] = hi;
    }
}

// bcat[o] = sum_c ln_b[c] * W[c][o], coalesced
__global__ void fold_b_kernel(const float* __restrict__ Wk, const float* __restrict__ Wv,
                              const float* __restrict__ lnkb, const float* __restrict__ lnvb,
                              float* __restrict__ bcat) {
    int seg = blockIdx.x, tid = threadIdx.x;
    int i = seg >> 1, isv = seg & 1;
    const float* W = (isv ? Wv : Wk) + i * 65536;
    const float* b = (isv ? lnvb : lnkb) + i * 256;
    float s = 0.f;
#pragma unroll 8
    for (int c = 0; c < 256; c++) s = fmaf(b[c], W[(size_t)c * 256 + tid], s);
    bcat[seg * 256 + tid] = s;
}

// batched weight split-transpose: src (K x N fp32) -> dst (N x 3K bf16) [hi|lo|hi]
struct WtJob { const float* src; __nv_bfloat16* dst; int K; int N; };
struct WtJobs { WtJob j[8]; };
__global__ void wtsplit_kernel(WtJobs jobs) {
    __shared__ float t[32][33];
    WtJob jb = jobs.j[blockIdx.z];
    int k0 = blockIdx.x * 32, n0 = blockIdx.y * 32;
    if (k0 >= jb.K || n0 >= jb.N) return;
    int tx = threadIdx.x, ty = threadIdx.y;
#pragma unroll
    for (int s = 0; s < 4; s++) {
        int k = k0 + ty + s * 8;
        t[ty + s * 8][tx] = jb.src[(size_t)k * jb.N + n0 + tx];
    }
    __syncthreads();
    int K = jb.K;
#pragma unroll
    for (int s = 0; s < 4; s++) {
        int n = n0 + ty + s * 8;
        float v = t[tx][ty + s * 8];
        __nv_bfloat16 hi, lo;
        split_bf16(v, hi, lo);
        size_t rb = (size_t)n * 3 * K;
        jb.dst[rb + k0 + tx] = hi;
        jb.dst[rb + K + k0 + tx] = lo;
        jb.dst[rb + 2 * K + k0 + tx] = hi;
    }
}

// LayerNorm, warp per row; optional fp32 out and/or cat [hi|hi|lo]
__global__ __launch_bounds__(256) void ln_kernel(const float* __restrict__ in,
                                                 const float* __restrict__ w,
                                                 const float* __restrict__ b,
                                                 float* __restrict__ outF,
                                                 __nv_bfloat16* __restrict__ outCat) {
    int wid = threadIdx.x >> 5, lane = threadIdx.x & 31;
    int m = blockIdx.x * 8 + wid;
    const float4* ip = (const float4*)(in + (size_t)m * 256 + lane * 8);
    float4 v0 = ip[0], v1 = ip[1];
    float s = v0.x + v0.y + v0.z + v0.w + v1.x + v1.y + v1.z + v1.w;
#pragma unroll
    for (int o = 16; o; o >>= 1) s += __shfl_xor_sync(0xffffffffu, s, o);
    float mean = s * (1.f / 256.f);
    float x[8] = {v0.x - mean, v0.y - mean, v0.z - mean, v0.w - mean,
                  v1.x - mean, v1.y - mean, v1.z - mean, v1.w - mean};
    float q = 0.f;
#pragma unroll
    for (int e = 0; e < 8; e++) q = fmaf(x[e], x[e], q);
#pragma unroll
    for (int o = 16; o; o >>= 1) q += __shfl_xor_sync(0xffffffffu, q, o);
    float rstd = rsqrtf(q * (1.f / 256.f) + 1e-5f);
    float4 w0 = *(const float4*)(w + lane * 8), w1 = *(const float4*)(w + lane * 8 + 4);
    float4 b0 = *(const float4*)(b + lane * 8), b1 = *(const float4*)(b + lane * 8 + 4);
    float y[8];
    y[0] = x[0] * rstd * w0.x + b0.x; y[1] = x[1] * rstd * w0.y + b0.y;
    y[2] = x[2] * rstd * w0.z + b0.z; y[3] = x[3] * rstd * w0.w + b0.w;
    y[4] = x[4] * rstd * w1.x + b1.x; y[5] = x[5] * rstd * w1.y + b1.y;
    y[6] = x[6] * rstd * w1.z + b1.z; y[7] = x[7] * rstd * w1.w + b1.w;
    if (outF) {
        float4* op = (float4*)(outF + (size_t)m * 256 + lane * 8);
        op[0] = make_float4(y[0], y[1], y[2], y[3]);
        op[1] = make_float4(y[4], y[5], y[6], y[7]);
    }
    if (outCat) {
        __nv_bfloat16 h[8], l[8];
#pragma unroll
        for (int e = 0; e < 8; e++) split_bf16(y[e], h[e], l[e]);
        size_t rb = (size_t)m * 768 + lane * 8;
        *(uint4*)(outCat + rb) = *(uint4*)h;
        *(uint4*)(outCat + rb + 256) = *(uint4*)h;
        *(uint4*)(outCat + rb + 512) = *(uint4*)l;
    }
}

__global__ __launch_bounds__(256) void invnorm_kernel(const float* __restrict__ x,
                                                      float* __restrict__ inv) {
    int wid = threadIdx.x >> 5, lane = threadIdx.x & 31;
    int m = blockIdx.x * 8 + wid;
    const float4* ip = (const float4*)(x + (size_t)m * 256 + lane * 8);
    float4 v0 = ip[0], v1 = ip[1];
    float q = v0.x * v0.x + v0.y * v0.y + v0.z * v0.z + v0.w * v0.w +
              v1.x * v1.x + v1.y * v1.y + v1.z * v1.z + v1.w * v1.w;
#pragma unroll
    for (int o = 16; o; o >>= 1) q += __shfl_xor_sync(0xffffffffu, q, o);
    if (lane == 0) inv[m] = 1.f / fmaxf(sqrtf(q), 1e-12f);
}

__global__ void transpose_scale(const float* __restrict__ in, float* __restrict__ out,
                                int R, int Cd, const float* __restrict__ scale) {
    __shared__ float t[32][33];
    int bx = blockIdx.x * 32, by = blockIdx.y * 32;
    int x = threadIdx.x, y0 = threadIdx.y;
    for (int yy = y0; yy < 32; yy += 8) {
        float s = scale ? scale[by + yy] : 1.f;
        t[yy][x] = in[(size_t)(by + yy) * Cd + bx + x] * s;
    }
    __syncthreads();
    for (int yy = y0; yy < 32; yy += 8)
        out[(size_t)(bx + yy) * R + by + x] = t[x][yy];
}

// =================== attention: warp per head, shuffle-lite ===================
__global__ __launch_bounds__(256) void attn_kernel(const float* __restrict__ q,
                                                   const float* __restrict__ KV,
                                                   const int* __restrict__ jLarr,
                                                   const int* __restrict__ jRarr,
                                                   int kvOff,
                                                   __nv_bfloat16* __restrict__ acat) {
    int m = blockIdx.x;
    int h = threadIdx.x >> 5, lane = threadIdx.x & 31;
    int jl = jLarr[m], jr = jRarr[m];
    int base = kvOff + h * 32;
    float qv = q[(size_t)m * 256 + h * 32 + lane] * ATTN_SCALE;
    // QK: lane owns n0=lane (left) and n1=lane+32 (right)
    const float* k0p = KV + (size_t)((lane << 7) + jl) * 1024 + base;
    const float* k1p = KV + (size_t)((lane << 7) + jr) * 1024 + base;
    float d0 = 0.f, d1 = 0.f;
#pragma unroll
    for (int d = 0; d < 32; d++) {
        float qd = __shfl_sync(0xffffffffu, qv, d);
        d0 = fmaf(qd, k0p[d], d0);
        d1 = fmaf(qd, k1p[d], d1);
    }
    float mx = fmaxf(d0, d1);
#pragma unroll
    for (int o = 16; o; o >>= 1) mx = fmaxf(mx, __shfl_xor_sync(0xffffffffu, mx, o));
    float e0 = expf(d0 - mx), e1 = expf(d1 - mx);
    float s = e0 + e1;
#pragma unroll
    for (int o = 16; o; o >>= 1) s += __shfl_xor_sync(0xffffffffu, s, o);
    float invs = 1.f / s;
    float p0 = e0 * invs, p1 = e1 * invs;
    // AV: lane owns dim d=lane (coalesced V reads)
    const float* vcol = KV + base + 256 + lane;
    float acc = 0.f;
#pragma unroll
    for (int n = 0; n < 64; n++) {
        float pn = __shfl_sync(0xffffffffu, (n < 32) ? p0 : p1, n & 31);
        int j = ((n & 31) << 7) + ((n < 32) ? jl : jr);
        acc = fmaf(pn, vcol[(size_t)j * 1024], acc);
    }
    int col = h * 32 + lane;
    __nv_bfloat16 hi, lo;
    split_bf16(acc, hi, lo);
    size_t rb = (size_t)m * 768;
    acat[rb + col] = hi;
    acat[rb + 256 + col] = hi;
    acat[rb + 512 + col] = lo;
}

// =================== mma.sync bf16 GEMM, tile 64x64, 4-stage ===================
// A: M x KA rows; B: N x KA rows (col-major B). 8 warps (4m x 2n), warp tile 16x32.
// EPI 0: Cf = acc (+bias)  EPI 1: Ccat = split(gelu(acc+bias)) [hi|hi|lo]  EPI 2: +bias+resid
#define KSTR 80
#define STGB 10240  // A 64*80 + B 64*80
template <int EPI>
__global__ __launch_bounds__(256, 2) void mma_gemm(const __nv_bfloat16* __restrict__ A,
                                                   const __nv_bfloat16* __restrict__ B,
                                                   const float* __restrict__ bias,
                                                   const float* __restrict__ resid,
                                                   float* __restrict__ Cf,
                                                   __nv_bfloat16* __restrict__ Ccat,
                                                   int KA, int N) {
    __shared__ __align__(16) char sm[4 * STGB];
    uint32_t smBase = smem_u32(sm);
    int tid = threadIdx.x, wid = tid >> 5, lane = tid & 31;
    int wm = wid >> 1, wn = wid & 1;
    int m0 = blockIdx.y << 6, n0 = blockIdx.x << 6;
    int niter = KA >> 5;

    float acc[4][4];
#pragma unroll
    for (int j = 0; j < 4; j++)
#pragma unroll
        for (int e = 0; e < 4; e++) acc[j][e] = 0.f;

    int crow = tid >> 2, cch = tid & 3;
    const __nv_bfloat16* gA = A + (size_t)(m0 + crow) * KA + (cch << 3);
    const __nv_bfloat16* gB = B + (size_t)(n0 + crow) * KA + (cch << 3);
    uint32_t sOff = crow * KSTR + (cch << 4);

#pragma unroll
    for (int s = 0; s < 3; s++) {
        cp16(smBase + s * STGB + sOff, gA + (s << 5));
        cp16(smBase + s * STGB + 5120 + sOff, gB + (s << 5));
        cp_commit();
    }

    uint32_t aOff = (wm * 16 + (lane & 15)) * KSTR + ((lane >> 4) << 4);
    uint32_t bOff = 5120 + (wn * 32 + (lane & 7) + ((lane >> 4) << 3)) * KSTR +
                    (((lane >> 3) & 1) << 4);

    for (int it = 0; it < niter; ++it) {
        int pre = it + 3;
        if (pre < niter) {
            uint32_t dst = smBase + (pre & 3) * STGB;
            cp16(dst + sOff, gA + (pre << 5));
            cp16(dst + 5120 + sOff, gB + (pre << 5));
        }
        cp_commit();
        cp_wait3();
        __syncthreads();
        uint32_t base = smBase + (it & 3) * STGB;
#pragma unroll
        for (int ks = 0; ks < 2; ks++) {
            uint32_t a[4], b[2][4];
            ldsm4(a, base + aOff + ks * 32);
            ldsm4(b[0], base + bOff + ks * 32);
            ldsm4(b[1], base + bOff + 16 * KSTR + ks * 32);
#pragma unroll
            for (int j = 0; j < 4; j++) {
                uint32_t b0 = b[j >> 1][(j & 1) ? 2 : 0];
                uint32_t b1 = b[j >> 1][(j & 1) ? 3 : 1];
                mma16816(acc[j], a, b0, b1);
            }
        }
        __syncthreads();
    }

    int row0 = m0 + wm * 16 + (lane >> 2);
    int row1 = row0 + 8;
#pragma unroll
    for (int j = 0; j < 4; j++) {
        int col = n0 + wn * 32 + j * 8 + ((lane & 3) << 1);
        float v0 = acc[j][0], v1 = acc[j][1], v2 = acc[j][2], v3 = acc[j][3];
        if (EPI != 0 || bias) {
            float b0 = bias[col], b1 = bias[col + 1];
            v0 += b0; v1 += b1; v2 += b0; v3 += b1;
        }
        if (EPI == 1) {
            v0 = 0.5f * v0 * (1.f + erff(v0 * 0.70710678118654752f));
            v1 = 0.5f * v1 * (1.f + erff(v1 * 0.70710678118654752f));
            v2 = 0.5f * v2 * (1.f + erff(v2 * 0.70710678118654752f));
            v3 = 0.5f * v3 * (1.f + erff(v3 * 0.70710678118654752f));
            __nv_bfloat16 h0, l0, h1, l1, h2, l2, h3, l3;
            split_bf16(v0, h0, l0); split_bf16(v1, h1, l1);
            split_bf16(v2, h2, l2); split_bf16(v3, h3, l3);
            size_t rb0 = (size_t)row0 * 3 * N + col;
            size_t rb1 = (size_t)row1 * 3 * N + col;
            *(__nv_bfloat162*)(Ccat + rb0) = __nv_bfloat162(h0, h1);
            *(__nv_bfloat162*)(Ccat + rb0 + N) = __nv_bfloat162(h0, h1);
            *(__nv_bfloat162*)(Ccat + rb0 + 2 * N) = __nv_bfloat162(l0, l1);
            *(__nv_bfloat162*)(Ccat + rb1) = __nv_bfloat162(h2, h3);
            *(__nv_bfloat162*)(Ccat + rb1 + N) = __nv_bfloat162(h2, h3);
            *(__nv_bfloat162*)(Ccat + rb1 + 2 * N) = __nv_bfloat162(l2, l3);
        } else {
            if (EPI == 2) {
                float2 r0 = *(const float2*)(resid + (size_t)row0 * N + col);
                float2 r1 = *(const float2*)(resid + (size_t)row1 * N + col);
                v0 += r0.x; v1 += r0.y; v2 += r1.x; v3 += r1.y;
            }
            *(float2*)(Cf + (size_t)row0 * N + col) = make_float2(v0, v1);
            *(float2*)(Cf + (size_t)row1 * N + col) = make_float2(v2, v3);
        }
    }
}

// =================== host launch ===================
extern "C" void kernel_launch(void* const* d_in, const int* in_sizes, int n_in,
                              void* d_out, int out_size) {
    (void)in_sizes; (void)n_in; (void)out_size;
    const float* grd2sat = (const float*)d_in[0];
    const float* grd_x   = (const float*)d_in[1];
    const float* u       = (const float*)d_in[2];
    const float* ln_q_w  = (const float*)d_in[3];
    const float* ln_q_b  = (const float*)d_in[4];
    const float* ln_k_w  = (const float*)d_in[5];
    const float* ln_k_b  = (const float*)d_in[6];
    const float* ln_v_w  = (const float*)d_in[7];
    const float* ln_v_b  = (const float*)d_in[8];
    const float* Wq      = (const float*)d_in[9];
    const float* Wk      = (const float*)d_in[10];
    const float* Wv      = (const float*)d_in[11];
    const float* Wproj   = (const float*)d_in[12];
    const float* bproj   = (const float*)d_in[13];
    const float* ln_pre_w  = (const float*)d_in[14];
    const float* ln_pre_b  = (const float*)d_in[15];
    const float* Wm1     = (const float*)d_in[16];
    const float* bm1     = (const float*)d_in[17];
    const float* Wm2     = (const float*)d_in[18];
    const float* bm2     = (const float*)d_in[19];
    const float* ln_post_w = (const float*)d_in[20];
    const float* ln_post_b = (const float*)d_in[21];
    float* out = (float*)d_out;

    __nv_bfloat16 *Xncat, *Wkvcat, *tcat, *acat, *z2cat, *hcat, *Wq2, *Wp2, *Wm1c, *Wm2c;
    float *bcat, *KV, *x, *q, *z1, *z2, *z3, *inv;
    int *jL, *jR;
    cudaGetSymbolAddress((void**)&Xncat, g_Xncat);
    cudaGetSymbolAddress((void**)&Wkvcat, g_Wkvcat);
    cudaGetSymbolAddress((void**)&bcat, g_bcat);
    cudaGetSymbolAddress((void**)&KV, g_KV);
    cudaGetSymbolAddress((void**)&x, g_x);
    cudaGetSymbolAddress((void**)&tcat, g_tcat);
    cudaGetSymbolAddress((void**)&q, g_q);
    cudaGetSymbolAddress((void**)&acat, g_acat);
    cudaGetSymbolAddress((void**)&z1, g_z1);
    cudaGetSymbolAddress((void**)&z2, g_z2);
    cudaGetSymbolAddress((void**)&z2cat, g_z2cat);
    cudaGetSymbolAddress((void**)&hcat, g_hcat);
    cudaGetSymbolAddress((void**)&z3, g_z3);
    cudaGetSymbolAddress((void**)&Wq2, g_Wq2);
    cudaGetSymbolAddress((void**)&Wp2, g_Wp2);
    cudaGetSymbolAddress((void**)&Wm1c, g_Wm1c);
    cudaGetSymbolAddress((void**)&Wm2c, g_Wm2c);
    cudaGetSymbolAddress((void**)&inv, g_inv);
    cudaGetSymbolAddress((void**)&jL, g_jL);
    cudaGetSymbolAddress((void**)&jR, g_jR);

    // ---- prep (once) ----
    idx_kernel<<<16, 256>>>(u, jL, jR);
    colnorm_kernel<<<128, 256>>>(grd_x, Xncat);
    fold_w_kernel<<<dim3(8, 8, 4), dim3(32, 8)>>>(Wk, Wv, ln_k_w, ln_v_w, Wkvcat);
    fold_b_kernel<<<4, 256>>>(Wk, Wv, ln_k_b, ln_v_b, bcat);

    WtJobs jobs;
    for (int i = 0; i < 2; i++) {
        jobs.j[i * 4 + 0] = {Wq + i * 65536, Wq2 + i * 256 * 768, 256, 256};
        jobs.j[i * 4 + 1] = {Wproj + i * 65536, Wp2 + i * 256 * 768, 256, 256};
        jobs.j[i * 4 + 2] = {Wm1 + i * 131072, Wm1c + i * 512 * 768, 256, 512};
        jobs.j[i * 4 + 3] = {Wm2 + i * 131072, Wm2c + i * 256 * 1536, 512, 256};
    }
    wtsplit_kernel<<<dim3(16, 16, 8), dim3(32, 8)>>>(jobs);

    // KV = Xn @ Wkv + bcat : (4096 x 1024)
    mma_gemm<0><<<dim3(16, 64), 256>>>(Xncat, Wkvcat, bcat, nullptr, KV, nullptr, 768, 1024);
    transpose_scale<<<dim3(128, 8), dim3(32, 8)>>>(grd2sat, x, 256, 4096, nullptr);

    for (int i = 0; i < 2; i++) {
        ln_kernel<<<512, 256>>>(x, ln_q_w + i * 256, ln_q_b + i * 256, nullptr, tcat);
        mma_gemm<0><<<dim3(4, 64), 256>>>(tcat, Wq2 + i * 256 * 768, nullptr, nullptr, q,
                                          nullptr, 768, 256);
        attn_kernel<<<4096, 256>>>(q, KV, jL, jR, i * 512, acat);
        mma_gemm<0><<<dim3(4, 64), 256>>>(acat, Wp2 + i * 256 * 768, bproj + i * 256,
                                          nullptr, z1, nullptr, 768, 256);
        ln_kernel<<<512, 256>>>(z1, ln_pre_w + i * 256, ln_pre_b + i * 256, z2, z2cat);
        mma_gemm<1><<<dim3(8, 64), 256>>>(z2cat, Wm1c + i * 512 * 768, bm1 + i * 512,
                                          nullptr, nullptr, hcat, 768, 512);
        mma_gemm<2><<<dim3(4, 64), 256>>>(hcat, Wm2c + i * 256 * 1536, bm2 + i * 256, z2,
                                          z3, nullptr, 1536, 256);
        ln_kernel<<<512, 256>>>(z3, ln_post_w + i * 256, ln_post_b + i * 256, x, nullptr);
    }

    invnorm_kernel<<<512, 256>>>(x, inv);
    transpose_scale<<<dim3(8, 128), dim3(32, 8)>>>(x, out, 4096, 256, inv);
}

// round 5
// speedup vs baseline: 1.9034x; 1.9034x over previous
#include <cuda_runtime.h>
#include <cuda_bf16.h>
#include <math.h>
#include <stdint.h>

#define ATTN_SCALE 0.17677669529663687f  // 32^-0.5

__device__ __forceinline__ uint32_t smem_u32(const void* p) {
    uint32_t a;
    asm("{ .reg .u64 t; cvta.to.shared.u64 t, %1; cvt.u32.u64 %0, t; }" : "=r"(a) : "l"(p));
    return a;
}
__device__ __forceinline__ void cp16(uint32_t s, const void* g) {
    asm volatile("cp.async.cg.shared.global [%0], [%1], 16;" :: "r"(s), "l"(g));
}
__device__ __forceinline__ void cp_commit() { asm volatile("cp.async.commit_group;"); }
__device__ __forceinline__ void cp_wait1() { asm volatile("cp.async.wait_group 1;"); }
__device__ __forceinline__ void ldsm4(uint32_t r[4], uint32_t addr) {
    asm volatile("ldmatrix.sync.aligned.m8n8.x4.shared.b16 {%0,%1,%2,%3}, [%4];"
                 : "=r"(r[0]), "=r"(r[1]), "=r"(r[2]), "=r"(r[3]) : "r"(addr));
}
__device__ __forceinline__ void mma16816(float c[4], const uint32_t a[4], uint32_t b0,
                                         uint32_t b1) {
    asm volatile(
        "mma.sync.aligned.m16n8k16.row.col.f32.bf16.bf16.f32 "
        "{%0,%1,%2,%3}, {%4,%5,%6,%7}, {%8,%9}, {%0,%1,%2,%3};"
        : "+f"(c[0]), "+f"(c[1]), "+f"(c[2]), "+f"(c[3])
        : "r"(a[0]), "r"(a[1]), "r"(a[2]), "r"(a[3]), "r"(b0), "r"(b1));
}
__device__ __forceinline__ void split_bf16(float v, __nv_bfloat16& hi, __nv_bfloat16& lo) {
    hi = __float2bfloat16(v);
    lo = __float2bfloat16(v - __bfloat162float(hi));
}

// =================== device scratch ===================
__device__ __nv_bfloat16 g_Xncat[4096 * 768];
__device__ __nv_bfloat16 g_Wkvcat[1024 * 768];
__device__ float g_bcat[1024];
__device__ float g_KV[4096 * 1024];
__device__ float g_x[4096 * 256];
__device__ __nv_bfloat16 g_tcat[4096 * 768];
__device__ float g_q[4096 * 256];
__device__ __nv_bfloat16 g_acat[4096 * 768];
__device__ float g_z1[4096 * 256];
__device__ float g_z2[4096 * 256];
__device__ __nv_bfloat16 g_z2cat[4096 * 768];
__device__ __nv_bfloat16 g_hcat[4096 * 1536];
__device__ float g_z3[4096 * 256];
__device__ __nv_bfloat16 g_Wq2[2 * 256 * 768];
__device__ __nv_bfloat16 g_Wp2[2 * 256 * 768];
__device__ __nv_bfloat16 g_Wm1c[2 * 512 * 768];
__device__ __nv_bfloat16 g_Wm2c[2 * 256 * 1536];
__device__ float g_inv[4096];
__device__ int g_jL[4096], g_jR[4096];

// =================== small prep kernels ===================
__global__ void idx_kernel(const float* __restrict__ u, int* __restrict__ jL,
                           int* __restrict__ jR) {
    int m = blockIdx.x * 256 + threadIdx.x;
    float uf = floorf(u[m]);
    jL[m] = (int)fminf(fmaxf(uf, 0.f), 127.f);
    jR[m] = (int)fminf(fmaxf(uf + 1.f, 0.f), 127.f);
}

// column-LN of grd_x (C=256 rows, 4096 cols) -> cat rows [hi|hi|lo], coalesced
__global__ __launch_bounds__(256) void colnorm_kernel(const float* __restrict__ gx,
                                                      __nv_bfloat16* __restrict__ cat) {
    __shared__ float tile[256][33];
    __shared__ float ps[8][32], pq[8][32];
    __shared__ float cmu[32], crs[32];
    int tx = threadIdx.x & 31, ty = threadIdx.x >> 5;
    int j0 = blockIdx.x * 32;
    float s = 0.f, q = 0.f;
#pragma unroll
    for (int t = 0; t < 32; t++) {
        int c = t * 8 + ty;
        float v = gx[(size_t)c * 4096 + j0 + tx];
        tile[c][tx] = v;
        s += v; q += v * v;
    }
    ps[ty][tx] = s; pq[ty][tx] = q;
    __syncthreads();
    if (ty == 0) {
        float ss = 0.f, qq = 0.f;
#pragma unroll
        for (int r = 0; r < 8; r++) { ss += ps[r][tx]; qq += pq[r][tx]; }
        float mu = ss * (1.f / 256.f);
        cmu[tx] = mu;
        crs[tx] = rsqrtf(qq * (1.f / 256.f) - mu * mu + 1e-5f);
    }
    __syncthreads();
    int lane = tx, w = ty;
#pragma unroll
    for (int r = 0; r < 4; r++) {
        int jj = w * 4 + r;
        float mu = cmu[jj], rs = crs[jj];
        size_t rb = (size_t)(j0 + jj) * 768 + lane * 8;
        __nv_bfloat16 h[8], l[8];
#pragma unroll
        for (int e = 0; e < 8; e++) {
            float v = (tile[lane * 8 + e][jj] - mu) * rs;
            split_bf16(v, h[e], l[e]);
        }
        *(uint4*)(cat + rb) = *(uint4*)h;
        *(uint4*)(cat + rb + 256) = *(uint4*)h;
        *(uint4*)(cat + rb + 512) = *(uint4*)l;
    }
}

// KV weights -> cat rows [hi|lo|hi] with LN weight folded; tile transpose, coalesced
__global__ void fold_w_kernel(const float* __restrict__ Wk, const float* __restrict__ Wv,
                              const float* __restrict__ lnkw, const float* __restrict__ lnvw,
                              __nv_bfloat16* __restrict__ cat) {
    __shared__ float t[32][33];
    int seg = blockIdx.z;          // 0..3 -> [k0,v0,k1,v1]
    int i = seg >> 1, isv = seg & 1;
    const float* W = (isv ? Wv : Wk) + i * 65536;
    const float* lw = (isv ? lnvw : lnkw) + i * 256;
    int c0 = blockIdx.x * 32, o0 = blockIdx.y * 32;
    int tx = threadIdx.x, ty = threadIdx.y;
#pragma unroll
    for (int s = 0; s < 4; s++) {
        int c = c0 + ty + s * 8;
        t[ty + s * 8][tx] = W[(size_t)c * 256 + o0 + tx] * lw[c];
    }
    __syncthreads();
#pragma unroll
    for (int s = 0; s < 4; s++) {
        int o = o0 + ty + s * 8;
        float v = t[tx][ty + s * 8];
        __nv_bfloat16 hi, lo;
        split_bf16(v, hi, lo);
        size_t rb = (size_t)(seg * 256 + o) * 768;
        cat[rb + c0 + tx] = hi;
        cat[rb + 256 + c0 + tx] = lo;
        cat[rb + 512 + c0 + tx] = hi;
    }
}

// bcat[o] = sum_c ln_b[c] * W[c][o] ; warp per output (R3-proven)
__global__ void fold_b_kernel(const float* __restrict__ Wk, const float* __restrict__ Wv,
                              const float* __restrict__ lnkb, const float* __restrict__ lnvb,
                              float* __restrict__ bcat) {
    int wid = threadIdx.x >> 5, lane = threadIdx.x & 31;
    int o = blockIdx.x * 8 + wid;  // grid 128
    int seg = o >> 8, oo = o & 255;
    int i = seg >> 1, isv = seg & 1;
    const float* W = (isv ? Wv : Wk) + i * 65536;
    const float* b = (isv ? lnvb : lnkb) + i * 256;
    float s = 0.f;
#pragma unroll
    for (int t = 0; t < 8; t++) {
        int c = lane + t * 32;
        s += b[c] * W[(size_t)c * 256 + oo];
    }
#pragma unroll
    for (int off = 16; off; off >>= 1) s += __shfl_xor_sync(0xffffffffu, s, off);
    if (lane == 0) bcat[o] = s;
}

// batched weight split-transpose: src (K x N fp32) -> dst (N x 3K bf16) [hi|lo|hi]
struct WtJob { const float* src; __nv_bfloat16* dst; int K; int N; };
struct WtJobs { WtJob j[8]; };
__global__ void wtsplit_kernel(WtJobs jobs) {
    __shared__ float t[32][33];
    WtJob jb = jobs.j[blockIdx.z];
    int k0 = blockIdx.x * 32, n0 = blockIdx.y * 32;
    if (k0 >= jb.K || n0 >= jb.N) return;
    int tx = threadIdx.x, ty = threadIdx.y;
#pragma unroll
    for (int s = 0; s < 4; s++) {
        int k = k0 + ty + s * 8;
        t[ty + s * 8][tx] = jb.src[(size_t)k * jb.N + n0 + tx];
    }
    __syncthreads();
    int K = jb.K;
#pragma unroll
    for (int s = 0; s < 4; s++) {
        int n = n0 + ty + s * 8;
        float v = t[tx][ty + s * 8];
        __nv_bfloat16 hi, lo;
        split_bf16(v, hi, lo);
        size_t rb = (size_t)n * 3 * K;
        jb.dst[rb + k0 + tx] = hi;
        jb.dst[rb + K + k0 + tx] = lo;
        jb.dst[rb + 2 * K + k0 + tx] = hi;
    }
}

// LayerNorm, warp per row; optional fp32 out and/or cat [hi|hi|lo]
__global__ __launch_bounds__(256) void ln_kernel(const float* __restrict__ in,
                                                 const float* __restrict__ w,
                                                 const float* __restrict__ b,
                                                 float* __restrict__ outF,
                                                 __nv_bfloat16* __restrict__ outCat) {
    int wid = threadIdx.x >> 5, lane = threadIdx.x & 31;
    int m = blockIdx.x * 8 + wid;
    const float4* ip = (const float4*)(in + (size_t)m * 256 + lane * 8);
    float4 v0 = ip[0], v1 = ip[1];
    float s = v0.x + v0.y + v0.z + v0.w + v1.x + v1.y + v1.z + v1.w;
#pragma unroll
    for (int o = 16; o; o >>= 1) s += __shfl_xor_sync(0xffffffffu, s, o);
    float mean = s * (1.f / 256.f);
    float x[8] = {v0.x - mean, v0.y - mean, v0.z - mean, v0.w - mean,
                  v1.x - mean, v1.y - mean, v1.z - mean, v1.w - mean};
    float q = 0.f;
#pragma unroll
    for (int e = 0; e < 8; e++) q = fmaf(x[e], x[e], q);
#pragma unroll
    for (int o = 16; o; o >>= 1) q += __shfl_xor_sync(0xffffffffu, q, o);
    float rstd = rsqrtf(q * (1.f / 256.f) + 1e-5f);
    float4 w0 = *(const float4*)(w + lane * 8), w1 = *(const float4*)(w + lane * 8 + 4);
    float4 b0 = *(const float4*)(b + lane * 8), b1 = *(const float4*)(b + lane * 8 + 4);
    float y[8];
    y[0] = x[0] * rstd * w0.x + b0.x; y[1] = x[1] * rstd * w0.y + b0.y;
    y[2] = x[2] * rstd * w0.z + b0.z; y[3] = x[3] * rstd * w0.w + b0.w;
    y[4] = x[4] * rstd * w1.x + b1.x; y[5] = x[5] * rstd * w1.y + b1.y;
    y[6] = x[6] * rstd * w1.z + b1.z; y[7] = x[7] * rstd * w1.w + b1.w;
    if (outF) {
        float4* op = (float4*)(outF + (size_t)m * 256 + lane * 8);
        op[0] = make_float4(y[0], y[1], y[2], y[3]);
        op[1] = make_float4(y[4], y[5], y[6], y[7]);
    }
    if (outCat) {
        __nv_bfloat16 h[8], l[8];
#pragma unroll
        for (int e = 0; e < 8; e++) split_bf16(y[e], h[e], l[e]);
        size_t rb = (size_t)m * 768 + lane * 8;
        *(uint4*)(outCat + rb) = *(uint4*)h;
        *(uint4*)(outCat + rb + 256) = *(uint4*)h;
        *(uint4*)(outCat + rb + 512) = *(uint4*)l;
    }
}

__global__ __launch_bounds__(256) void invnorm_kernel(const float* __restrict__ x,
                                                      float* __restrict__ inv) {
    int wid = threadIdx.x >> 5, lane = threadIdx.x & 31;
    int m = blockIdx.x * 8 + wid;
    const float4* ip = (const float4*)(x + (size_t)m * 256 + lane * 8);
    float4 v0 = ip[0], v1 = ip[1];
    float q = v0.x * v0.x + v0.y * v0.y + v0.z * v0.z + v0.w * v0.w +
              v1.x * v1.x + v1.y * v1.y + v1.z * v1.z + v1.w * v1.w;
#pragma unroll
    for (int o = 16; o; o >>= 1) q += __shfl_xor_sync(0xffffffffu, q, o);
    if (lane == 0) inv[m] = 1.f / fmaxf(sqrtf(q), 1e-12f);
}

__global__ void transpose_scale(const float* __restrict__ in, float* __restrict__ out,
                                int R, int Cd, const float* __restrict__ scale) {
    __shared__ float t[32][33];
    int bx = blockIdx.x * 32, by = blockIdx.y * 32;
    int x = threadIdx.x, y0 = threadIdx.y;
    for (int yy = y0; yy < 32; yy += 8) {
        float s = scale ? scale[by + yy] : 1.f;
        t[yy][x] = in[(size_t)(by + yy) * Cd + bx + x] * s;
    }
    __syncthreads();
    for (int yy = y0; yy < 32; yy += 8)
        out[(size_t)(bx + yy) * R + by + x] = t[x][yy];
}

// =================== attention (R3-proven: coalesced loads, warp reduce) ===========
__global__ __launch_bounds__(256) void attn_kernel(const float* __restrict__ q,
                                                   const float* __restrict__ KV,
                                                   const int* __restrict__ jLarr,
                                                   const int* __restrict__ jRarr,
                                                   int kvOff,
                                                   __nv_bfloat16* __restrict__ acat) {
    int m = blockIdx.x;
    int h = threadIdx.x >> 5;
    int lane = threadIdx.x & 31;
    int jL = jLarr[m], jR = jRarr[m];
    float qv = q[(size_t)m * 256 + h * 32 + lane] * ATTN_SCALE;
    int base = kvOff + h * 32 + lane;
    float d0 = 0.f, d1 = 0.f;
#pragma unroll
    for (int n = 0; n < 64; n++) {
        int w = (n < 32) ? jL : jR;
        int j = ((n & 31) << 7) + w;
        float p = KV[(size_t)j * 1024 + base] * qv;
        p += __shfl_xor_sync(0xffffffffu, p, 16);
        p += __shfl_xor_sync(0xffffffffu, p, 8);
        p += __shfl_xor_sync(0xffffffffu, p, 4);
        p += __shfl_xor_sync(0xffffffffu, p, 2);
        p += __shfl_xor_sync(0xffffffffu, p, 1);
        if (lane == (n & 31)) { if (n < 32) d0 = p; else d1 = p; }
    }
    float mx = fmaxf(d0, d1);
#pragma unroll
    for (int o = 16; o; o >>= 1) mx = fmaxf(mx, __shfl_xor_sync(0xffffffffu, mx, o));
    float e0 = expf(d0 - mx), e1 = expf(d1 - mx);
    float s = e0 + e1;
#pragma unroll
    for (int o = 16; o; o >>= 1) s += __shfl_xor_sync(0xffffffffu, s, o);
    float invs = 1.f / s;
    float p0 = e0 * invs, p1 = e1 * invs;
    float acc = 0.f;
#pragma unroll
    for (int n = 0; n < 64; n++) {
        float pn = __shfl_sync(0xffffffffu, (n < 32) ? p0 : p1, n & 31);
        int j = ((n & 31) << 7) + ((n < 32) ? jL : jR);
        acc = fmaf(pn, KV[(size_t)j * 1024 + base + 256], acc);
    }
    int col = h * 32 + lane;
    __nv_bfloat16 hi, lo;
    split_bf16(acc, hi, lo);
    size_t rb = (size_t)m * 768;
    acat[rb + col] = hi;
    acat[rb + 256 + col] = hi;
    acat[rb + 512 + col] = lo;
}

// =================== mma.sync bf16 GEMM (R3-proven: 128x64, 2-stage) ===================
// A: M x Krow rows; B: N x Krow rows (col-major B). 8 warps (4m x 2n), warp tile 32x32.
// EPI 0: Cf = acc (+bias)  EPI 1: Ccat = split(gelu(acc+bias)) [hi|hi|lo]  EPI 2: +bias+resid
#define ASTRIDE 80
#define STAGE_BYTES 15360  // A: 128*80=10240, B: 64*80=5120
template <int EPI>
__global__ __launch_bounds__(256, 2) void mma_gemm(const __nv_bfloat16* __restrict__ A,
                                                   const __nv_bfloat16* __restrict__ B,
                                                   const float* __restrict__ bias,
                                                   const float* __restrict__ resid,
                                                   float* __restrict__ Cf,
                                                   __nv_bfloat16* __restrict__ Ccat,
                                                   int Krow, int N) {
    __shared__ __align__(16) char sm[2 * STAGE_BYTES];
    uint32_t smBase = smem_u32(sm);
    int tid = threadIdx.x;
    int wid = tid >> 5, lane = tid & 31;
    int wm = wid >> 1, wn = wid & 1;
    int m0 = blockIdx.y << 7, n0 = blockIdx.x << 6;
    int niter = Krow >> 5;

    float acc[2][4][4];
#pragma unroll
    for (int t = 0; t < 2; t++)
#pragma unroll
        for (int j = 0; j < 4; j++)
#pragma unroll
            for (int e = 0; e < 4; e++) acc[t][j][e] = 0.f;

    int arow = tid >> 2, ach = tid & 3;

    uint32_t aOff = (uint32_t)((wm * 32 + (lane & 15)) * ASTRIDE + (((lane >> 4) << 3) << 1));
    uint32_t bOff = (uint32_t)((wn * 32 + (lane & 7) + ((lane >> 4) << 3)) * ASTRIDE +
                               ((((lane >> 3) & 1) << 3) << 1));

    // prologue: stage 0
    {
        const __nv_bfloat16* gA = A + (size_t)m0 * Krow;
#pragma unroll
        for (int i = 0; i < 2; i++) {
            int u = tid + (i << 8);
            int row = u >> 2, ch = u & 3;
            cp16(smBase + row * ASTRIDE + ch * 16, gA + (size_t)row * Krow + (ch << 3));
        }
        cp16(smBase + 10240 + arow * ASTRIDE + ach * 16,
             B + (size_t)(n0 + arow) * Krow + (ach << 3));
    }
    cp_commit();

    for (int it = 0; it < niter; ++it) {
        if (it + 1 < niter) {
            int st = (it + 1) & 1;
            int k0 = (it + 1) << 5;
            uint32_t sA = smBase + st * STAGE_BYTES;
            const __nv_bfloat16* gA = A + (size_t)m0 * Krow + k0;
#pragma unroll
            for (int i = 0; i < 2; i++) {
                int u = tid + (i << 8);
                int row = u >> 2, ch = u & 3;
                cp16(sA + row * ASTRIDE + ch * 16, gA + (size_t)row * Krow + (ch << 3));
            }
            cp16(sA + 10240 + arow * ASTRIDE + ach * 16,
                 B + (size_t)(n0 + arow) * Krow + k0 + (ach << 3));
        }
        cp_commit();
        cp_wait1();
        __syncthreads();

        uint32_t aBase = smBase + (it & 1) * STAGE_BYTES + aOff;
        uint32_t bBase = smBase + (it & 1) * STAGE_BYTES + 10240 + bOff;
#pragma unroll
        for (int ks = 0; ks < 2; ks++) {
            uint32_t a[2][4], b[2][4];
            ldsm4(a[0], aBase + ks * 32);
            ldsm4(a[1], aBase + 16 * ASTRIDE + ks * 32);
            ldsm4(b[0], bBase + ks * 32);
            ldsm4(b[1], bBase + 16 * ASTRIDE + ks * 32);
#pragma unroll
            for (int t = 0; t < 2; t++) {
#pragma unroll
                for (int j = 0; j < 4; j++) {
                    uint32_t b0 = b[j >> 1][(j & 1) ? 2 : 0];
                    uint32_t b1 = b[j >> 1][(j & 1) ? 3 : 1];
                    mma16816(acc[t][j], a[t], b0, b1);
                }
            }
        }
        __syncthreads();
    }

    // epilogue
#pragma unroll
    for (int t = 0; t < 2; t++) {
        int row0 = m0 + wm * 32 + t * 16 + (lane >> 2);
        int row1 = row0 + 8;
#pragma unroll
        for (int j = 0; j < 4; j++) {
            int col = n0 + wn * 32 + j * 8 + ((lane & 3) << 1);
            float v0 = acc[t][j][0], v1 = acc[t][j][1];
            float v2 = acc[t][j][2], v3 = acc[t][j][3];
            if (EPI != 0 || bias) {
                float b0 = bias[col], b1 = bias[col + 1];
                v0 += b0; v1 += b1; v2 += b0; v3 += b1;
            }
            if (EPI == 1) {
                v0 = 0.5f * v0 * (1.f + erff(v0 * 0.70710678118654752f));
                v1 = 0.5f * v1 * (1.f + erff(v1 * 0.70710678118654752f));
                v2 = 0.5f * v2 * (1.f + erff(v2 * 0.70710678118654752f));
                v3 = 0.5f * v3 * (1.f + erff(v3 * 0.70710678118654752f));
                __nv_bfloat16 h0, l0, h1, l1, h2, l2, h3, l3;
                split_bf16(v0, h0, l0); split_bf16(v1, h1, l1);
                split_bf16(v2, h2, l2); split_bf16(v3, h3, l3);
                size_t rb0 = (size_t)row0 * 3 * N + col;
                size_t rb1 = (size_t)row1 * 3 * N + col;
                *(__nv_bfloat162*)(Ccat + rb0) = __nv_bfloat162(h0, h1);
                *(__nv_bfloat162*)(Ccat + rb0 + N) = __nv_bfloat162(h0, h1);
                *(__nv_bfloat162*)(Ccat + rb0 + 2 * N) = __nv_bfloat162(l0, l1);
                *(__nv_bfloat162*)(Ccat + rb1) = __nv_bfloat162(h2, h3);
                *(__nv_bfloat162*)(Ccat + rb1 + N) = __nv_bfloat162(h2, h3);
                *(__nv_bfloat162*)(Ccat + rb1 + 2 * N) = __nv_bfloat162(l2, l3);
            } else {
                if (EPI == 2) {
                    float2 r0 = *(const float2*)(resid + (size_t)row0 * N + col);
                    float2 r1 = *(const float2*)(resid + (size_t)row1 * N + col);
                    v0 += r0.x; v1 += r0.y; v2 += r1.x; v3 += r1.y;
                }
                *(float2*)(Cf + (size_t)row0 * N + col) = make_float2(v0, v1);
                *(float2*)(Cf + (size_t)row1 * N + col) = make_float2(v2, v3);
            }
        }
    }
}

// =================== host launch ===================
extern "C" void kernel_launch(void* const* d_in, const int* in_sizes, int n_in,
                              void* d_out, int out_size) {
    (void)in_sizes; (void)n_in; (void)out_size;
    const float* grd2sat = (const float*)d_in[0];
    const float* grd_x   = (const float*)d_in[1];
    const float* u       = (const float*)d_in[2];
    const float* ln_q_w  = (const float*)d_in[3];
    const float* ln_q_b  = (const float*)d_in[4];
    const float* ln_k_w  = (const float*)d_in[5];
    const float* ln_k_b  = (const float*)d_in[6];
    const float* ln_v_w  = (const float*)d_in[7];
    const float* ln_v_b  = (const float*)d_in[8];
    const float* Wq      = (const float*)d_in[9];
    const float* Wk      = (const float*)d_in[10];
    const float* Wv      = (const float*)d_in[11];
    const float* Wproj   = (const float*)d_in[12];
    const float* bproj   = (const float*)d_in[13];
    const float* ln_pre_w  = (const float*)d_in[14];
    const float* ln_pre_b  = (const float*)d_in[15];
    const float* Wm1     = (const float*)d_in[16];
    const float* bm1     = (const float*)d_in[17];
    const float* Wm2     = (const float*)d_in[18];
    const float* bm2     = (const float*)d_in[19];
    const float* ln_post_w = (const float*)d_in[20];
    const float* ln_post_b = (const float*)d_in[21];
    float* out = (float*)d_out;

    __nv_bfloat16 *Xncat, *Wkvcat, *tcat, *acat, *z2cat, *hcat, *Wq2, *Wp2, *Wm1c, *Wm2c;
    float *bcat, *KV, *x, *q, *z1, *z2, *z3, *inv;
    int *jL, *jR;
    cudaGetSymbolAddress((void**)&Xncat, g_Xncat);
    cudaGetSymbolAddress((void**)&Wkvcat, g_Wkvcat);
    cudaGetSymbolAddress((void**)&bcat, g_bcat);
    cudaGetSymbolAddress((void**)&KV, g_KV);
    cudaGetSymbolAddress((void**)&x, g_x);
    cudaGetSymbolAddress((void**)&tcat, g_tcat);
    cudaGetSymbolAddress((void**)&q, g_q);
    cudaGetSymbolAddress((void**)&acat, g_acat);
    cudaGetSymbolAddress((void**)&z1, g_z1);
    cudaGetSymbolAddress((void**)&z2, g_z2);
    cudaGetSymbolAddress((void**)&z2cat, g_z2cat);
    cudaGetSymbolAddress((void**)&hcat, g_hcat);
    cudaGetSymbolAddress((void**)&z3, g_z3);
    cudaGetSymbolAddress((void**)&Wq2, g_Wq2);
    cudaGetSymbolAddress((void**)&Wp2, g_Wp2);
    cudaGetSymbolAddress((void**)&Wm1c, g_Wm1c);
    cudaGetSymbolAddress((void**)&Wm2c, g_Wm2c);
    cudaGetSymbolAddress((void**)&inv, g_inv);
    cudaGetSymbolAddress((void**)&jL, g_jL);
    cudaGetSymbolAddress((void**)&jR, g_jR);

    // ---- prep (once) ----
    idx_kernel<<<16, 256>>>(u, jL, jR);
    colnorm_kernel<<<128, 256>>>(grd_x, Xncat);
    fold_w_kernel<<<dim3(8, 8, 4), dim3(32, 8)>>>(Wk, Wv, ln_k_w, ln_v_w, Wkvcat);
    fold_b_kernel<<<128, 256>>>(Wk, Wv, ln_k_b, ln_v_b, bcat);

    WtJobs jobs;
    for (int i = 0; i < 2; i++) {
        jobs.j[i * 4 + 0] = {Wq + i * 65536, Wq2 + i * 256 * 768, 256, 256};
        jobs.j[i * 4 + 1] = {Wproj + i * 65536, Wp2 + i * 256 * 768, 256, 256};
        jobs.j[i * 4 + 2] = {Wm1 + i * 131072, Wm1c + i * 512 * 768, 256, 512};
        jobs.j[i * 4 + 3] = {Wm2 + i * 131072, Wm2c + i * 256 * 1536, 512, 256};
    }
    wtsplit_kernel<<<dim3(16, 16, 8), dim3(32, 8)>>>(jobs);

    // KV = Xn @ Wkv + bcat : (4096 x 1024)
    mma_gemm<0><<<dim3(16, 32), 256>>>(Xncat, Wkvcat, bcat, nullptr, KV, nullptr, 768, 1024);
    transpose_scale<<<dim3(128, 8), dim3(32, 8)>>>(grd2sat, x, 256, 4096, nullptr);

    for (int i = 0; i < 2; i++) {
        ln_kernel<<<512, 256>>>(x, ln_q_w + i * 256, ln_q_b + i * 256, nullptr, tcat);
        mma_gemm<0><<<dim3(4, 32), 256>>>(tcat, Wq2 + i * 256 * 768, nullptr, nullptr, q,
                                          nullptr, 768, 256);
        attn_kernel<<<4096, 256>>>(q, KV, jL, jR, i * 512, acat);
        mma_gemm<0><<<dim3(4, 32), 256>>>(acat, Wp2 + i * 256 * 768, bproj + i * 256,
                                          nullptr, z1, nullptr, 768, 256);
        ln_kernel<<<512, 256>>>(z1, ln_pre_w + i * 256, ln_pre_b + i * 256, z2, z2cat);
        mma_gemm<1><<<dim3(8, 32), 256>>>(z2cat, Wm1c + i * 512 * 768, bm1 + i * 512,
                                          nullptr, nullptr, hcat, 768, 512);
        mma_gemm<2><<<dim3(4, 32), 256>>>(hcat, Wm2c + i * 256 * 1536, bm2 + i * 256, z2,
                                          z3, nullptr, 1536, 256);
        ln_kernel<<<512, 256>>>(z3, ln_post_w + i * 256, ln_post_b + i * 256, x, nullptr);
    }

    invnorm_kernel<<<512, 256>>>(x, inv);
    transpose_scale<<<dim3(8, 128), dim3(32, 8)>>>(x, out, 4096, 256, inv);
}

// round 6
// speedup vs baseline: 1.9885x; 1.0447x over previous
#include <cuda_runtime.h>
#include <cuda_bf16.h>
#include <math.h>
#include <stdint.h>

#define ATTN_SCALE 0.17677669529663687f  // 32^-0.5

__device__ __forceinline__ uint32_t smem_u32(const void* p) {
    uint32_t a;
    asm("{ .reg .u64 t; cvta.to.shared.u64 t, %1; cvt.u32.u64 %0, t; }" : "=r"(a) : "l"(p));
    return a;
}
__device__ __forceinline__ void cp16(uint32_t s, const void* g) {
    asm volatile("cp.async.cg.shared.global [%0], [%1], 16;" :: "r"(s), "l"(g));
}
__device__ __forceinline__ void cp_commit() { asm volatile("cp.async.commit_group;"); }
__device__ __forceinline__ void cp_wait1() { asm volatile("cp.async.wait_group 1;"); }
__device__ __forceinline__ void ldsm4(uint32_t r[4], uint32_t addr) {
    asm volatile("ldmatrix.sync.aligned.m8n8.x4.shared.b16 {%0,%1,%2,%3}, [%4];"
                 : "=r"(r[0]), "=r"(r[1]), "=r"(r[2]), "=r"(r[3]) : "r"(addr));
}
__device__ __forceinline__ void mma16816(float c[4], const uint32_t a[4], uint32_t b0,
                                         uint32_t b1) {
    asm volatile(
        "mma.sync.aligned.m16n8k16.row.col.f32.bf16.bf16.f32 "
        "{%0,%1,%2,%3}, {%4,%5,%6,%7}, {%8,%9}, {%0,%1,%2,%3};"
        : "+f"(c[0]), "+f"(c[1]), "+f"(c[2]), "+f"(c[3])
        : "r"(a[0]), "r"(a[1]), "r"(a[2]), "r"(a[3]), "r"(b0), "r"(b1));
}
__device__ __forceinline__ void split_bf16(float v, __nv_bfloat16& hi, __nv_bfloat16& lo) {
    hi = __float2bfloat16(v);
    lo = __float2bfloat16(v - __bfloat162float(hi));
}

// =================== device scratch ===================
__device__ __nv_bfloat16 g_Xncat[4096 * 768];
__device__ __nv_bfloat16 g_Wkvcat[1024 * 768];
__device__ float g_bcat[1024];
__device__ float g_KV[4096 * 1024];
__device__ float g_x[4096 * 256];
__device__ __nv_bfloat16 g_tcat[4096 * 768];
__device__ float g_q[4096 * 256];
__device__ __nv_bfloat16 g_acat[4096 * 768];
__device__ float g_z1[4096 * 256];
__device__ float g_z2[4096 * 256];
__device__ __nv_bfloat16 g_z2cat[4096 * 768];
__device__ __nv_bfloat16 g_hcat[4096 * 1536];
__device__ float g_z3[4096 * 256];
__device__ __nv_bfloat16 g_Wq2[2 * 256 * 768];
__device__ __nv_bfloat16 g_Wp2[2 * 256 * 768];
__device__ __nv_bfloat16 g_Wm1c[2 * 512 * 768];
__device__ __nv_bfloat16 g_Wm2c[2 * 256 * 1536];
__device__ float g_inv[4096];
__device__ int g_jL[4096], g_jR[4096];

// =================== small prep kernels ===================
__global__ void idx_kernel(const float* __restrict__ u, int* __restrict__ jL,
                           int* __restrict__ jR) {
    int m = blockIdx.x * 256 + threadIdx.x;
    float uf = floorf(u[m]);
    jL[m] = (int)fminf(fmaxf(uf, 0.f), 127.f);
    jR[m] = (int)fminf(fmaxf(uf + 1.f, 0.f), 127.f);
}

// column-LN of grd_x (C=256 rows, 4096 cols) -> cat rows [hi|hi|lo], coalesced
__global__ __launch_bounds__(256) void colnorm_kernel(const float* __restrict__ gx,
                                                      __nv_bfloat16* __restrict__ cat) {
    __shared__ float tile[256][33];
    __shared__ float ps[8][32], pq[8][32];
    __shared__ float cmu[32], crs[32];
    int tx = threadIdx.x & 31, ty = threadIdx.x >> 5;
    int j0 = blockIdx.x * 32;
    float s = 0.f, q = 0.f;
#pragma unroll
    for (int t = 0; t < 32; t++) {
        int c = t * 8 + ty;
        float v = gx[(size_t)c * 4096 + j0 + tx];
        tile[c][tx] = v;
        s += v; q += v * v;
    }
    ps[ty][tx] = s; pq[ty][tx] = q;
    __syncthreads();
    if (ty == 0) {
        float ss = 0.f, qq = 0.f;
#pragma unroll
        for (int r = 0; r < 8; r++) { ss += ps[r][tx]; qq += pq[r][tx]; }
        float mu = ss * (1.f / 256.f);
        cmu[tx] = mu;
        crs[tx] = rsqrtf(qq * (1.f / 256.f) - mu * mu + 1e-5f);
    }
    __syncthreads();
    int lane = tx, w = ty;
#pragma unroll
    for (int r = 0; r < 4; r++) {
        int jj = w * 4 + r;
        float mu = cmu[jj], rs = crs[jj];
        size_t rb = (size_t)(j0 + jj) * 768 + lane * 8;
        __nv_bfloat16 h[8], l[8];
#pragma unroll
        for (int e = 0; e < 8; e++) {
            float v = (tile[lane * 8 + e][jj] - mu) * rs;
            split_bf16(v, h[e], l[e]);
        }
        *(uint4*)(cat + rb) = *(uint4*)h;
        *(uint4*)(cat + rb + 256) = *(uint4*)h;
        *(uint4*)(cat + rb + 512) = *(uint4*)l;
    }
}

// KV weights -> cat rows [hi|lo|hi] with LN weight folded; tile transpose, coalesced
__global__ void fold_w_kernel(const float* __restrict__ Wk, const float* __restrict__ Wv,
                              const float* __restrict__ lnkw, const float* __restrict__ lnvw,
                              __nv_bfloat16* __restrict__ cat) {
    __shared__ float t[32][33];
    int seg = blockIdx.z;          // 0..3 -> [k0,v0,k1,v1]
    int i = seg >> 1, isv = seg & 1;
    const float* W = (isv ? Wv : Wk) + i * 65536;
    const float* lw = (isv ? lnvw : lnkw) + i * 256;
    int c0 = blockIdx.x * 32, o0 = blockIdx.y * 32;
    int tx = threadIdx.x, ty = threadIdx.y;
#pragma unroll
    for (int s = 0; s < 4; s++) {
        int c = c0 + ty + s * 8;
        t[ty + s * 8][tx] = W[(size_t)c * 256 + o0 + tx] * lw[c];
    }
    __syncthreads();
#pragma unroll
    for (int s = 0; s < 4; s++) {
        int o = o0 + ty + s * 8;
        float v = t[tx][ty + s * 8];
        __nv_bfloat16 hi, lo;
        split_bf16(v, hi, lo);
        size_t rb = (size_t)(seg * 256 + o) * 768;
        cat[rb + c0 + tx] = hi;
        cat[rb + 256 + c0 + tx] = lo;
        cat[rb + 512 + c0 + tx] = hi;
    }
}

// bcat[o] = sum_c ln_b[c] * W[c][o] ; warp per output
__global__ void fold_b_kernel(const float* __restrict__ Wk, const float* __restrict__ Wv,
                              const float* __restrict__ lnkb, const float* __restrict__ lnvb,
                              float* __restrict__ bcat) {
    int wid = threadIdx.x >> 5, lane = threadIdx.x & 31;
    int o = blockIdx.x * 8 + wid;  // grid 128
    int seg = o >> 8, oo = o & 255;
    int i = seg >> 1, isv = seg & 1;
    const float* W = (isv ? Wv : Wk) + i * 65536;
    const float* b = (isv ? lnvb : lnkb) + i * 256;
    float s = 0.f;
#pragma unroll
    for (int t = 0; t < 8; t++) {
        int c = lane + t * 32;
        s += b[c] * W[(size_t)c * 256 + oo];
    }
#pragma unroll
    for (int off = 16; off; off >>= 1) s += __shfl_xor_sync(0xffffffffu, s, off);
    if (lane == 0) bcat[o] = s;
}

// batched weight split-transpose: src (K x N fp32) -> dst (N x 3K bf16) [hi|lo|hi]
struct WtJob { const float* src; __nv_bfloat16* dst; int K; int N; };
struct WtJobs { WtJob j[8]; };
__global__ void wtsplit_kernel(WtJobs jobs) {
    __shared__ float t[32][33];
    WtJob jb = jobs.j[blockIdx.z];
    int k0 = blockIdx.x * 32, n0 = blockIdx.y * 32;
    if (k0 >= jb.K || n0 >= jb.N) return;
    int tx = threadIdx.x, ty = threadIdx.y;
#pragma unroll
    for (int s = 0; s < 4; s++) {
        int k = k0 + ty + s * 8;
        t[ty + s * 8][tx] = jb.src[(size_t)k * jb.N + n0 + tx];
    }
    __syncthreads();
    int K = jb.K;
#pragma unroll
    for (int s = 0; s < 4; s++) {
        int n = n0 + ty + s * 8;
        float v = t[tx][ty + s * 8];
        __nv_bfloat16 hi, lo;
        split_bf16(v, hi, lo);
        size_t rb = (size_t)n * 3 * K;
        jb.dst[rb + k0 + tx] = hi;
        jb.dst[rb + K + k0 + tx] = lo;
        jb.dst[rb + 2 * K + k0 + tx] = hi;
    }
}

// LayerNorm, warp per row; optional fp32 out and/or cat [hi|hi|lo]
__global__ __launch_bounds__(256) void ln_kernel(const float* __restrict__ in,
                                                 const float* __restrict__ w,
                                                 const float* __restrict__ b,
                                                 float* __restrict__ outF,
                                                 __nv_bfloat16* __restrict__ outCat) {
    int wid = threadIdx.x >> 5, lane = threadIdx.x & 31;
    int m = blockIdx.x * 8 + wid;
    const float4* ip = (const float4*)(in + (size_t)m * 256 + lane * 8);
    float4 v0 = ip[0], v1 = ip[1];
    float s = v0.x + v0.y + v0.z + v0.w + v1.x + v1.y + v1.z + v1.w;
#pragma unroll
    for (int o = 16; o; o >>= 1) s += __shfl_xor_sync(0xffffffffu, s, o);
    float mean = s * (1.f / 256.f);
    float x[8] = {v0.x - mean, v0.y - mean, v0.z - mean, v0.w - mean,
                  v1.x - mean, v1.y - mean, v1.z - mean, v1.w - mean};
    float q = 0.f;
#pragma unroll
    for (int e = 0; e < 8; e++) q = fmaf(x[e], x[e], q);
#pragma unroll
    for (int o = 16; o; o >>= 1) q += __shfl_xor_sync(0xffffffffu, q, o);
    float rstd = rsqrtf(q * (1.f / 256.f) + 1e-5f);
    float4 w0 = *(const float4*)(w + lane * 8), w1 = *(const float4*)(w + lane * 8 + 4);
    float4 b0 = *(const float4*)(b + lane * 8), b1 = *(const float4*)(b + lane * 8 + 4);
    float y[8];
    y[0] = x[0] * rstd * w0.x + b0.x; y[1] = x[1] * rstd * w0.y + b0.y;
    y[2] = x[2] * rstd * w0.z + b0.z; y[3] = x[3] * rstd * w0.w + b0.w;
    y[4] = x[4] * rstd * w1.x + b1.x; y[5] = x[5] * rstd * w1.y + b1.y;
    y[6] = x[6] * rstd * w1.z + b1.z; y[7] = x[7] * rstd * w1.w + b1.w;
    if (outF) {
        float4* op = (float4*)(outF + (size_t)m * 256 + lane * 8);
        op[0] = make_float4(y[0], y[1], y[2], y[3]);
        op[1] = make_float4(y[4], y[5], y[6], y[7]);
    }
    if (outCat) {
        __nv_bfloat16 h[8], l[8];
#pragma unroll
        for (int e = 0; e < 8; e++) split_bf16(y[e], h[e], l[e]);
        size_t rb = (size_t)m * 768 + lane * 8;
        *(uint4*)(outCat + rb) = *(uint4*)h;
        *(uint4*)(outCat + rb + 256) = *(uint4*)h;
        *(uint4*)(outCat + rb + 512) = *(uint4*)l;
    }
}

__global__ __launch_bounds__(256) void invnorm_kernel(const float* __restrict__ x,
                                                      float* __restrict__ inv) {
    int wid = threadIdx.x >> 5, lane = threadIdx.x & 31;
    int m = blockIdx.x * 8 + wid;
    const float4* ip = (const float4*)(x + (size_t)m * 256 + lane * 8);
    float4 v0 = ip[0], v1 = ip[1];
    float q = v0.x * v0.x + v0.y * v0.y + v0.z * v0.z + v0.w * v0.w +
              v1.x * v1.x + v1.y * v1.y + v1.z * v1.z + v1.w * v1.w;
#pragma unroll
    for (int o = 16; o; o >>= 1) q += __shfl_xor_sync(0xffffffffu, q, o);
    if (lane == 0) inv[m] = 1.f / fmaxf(sqrtf(q), 1e-12f);
}

__global__ void transpose_scale(const float* __restrict__ in, float* __restrict__ out,
                                int R, int Cd, const float* __restrict__ scale) {
    __shared__ float t[32][33];
    int bx = blockIdx.x * 32, by = blockIdx.y * 32;
    int x = threadIdx.x, y0 = threadIdx.y;
    for (int yy = y0; yy < 32; yy += 8) {
        float s = scale ? scale[by + yy] : 1.f;
        t[yy][x] = in[(size_t)(by + yy) * Cd + bx + x] * s;
    }
    __syncthreads();
    for (int yy = y0; yy < 32; yy += 8)
        out[(size_t)(bx + yy) * R + by + x] = t[x][yy];
}

// =================== attention (R3/R5-proven: coalesced loads, warp reduce) ========
__global__ __launch_bounds__(256) void attn_kernel(const float* __restrict__ q,
                                                   const float* __restrict__ KV,
                                                   const int* __restrict__ jLarr,
                                                   const int* __restrict__ jRarr,
                                                   int kvOff,
                                                   __nv_bfloat16* __restrict__ acat) {
    int m = blockIdx.x;
    int h = threadIdx.x >> 5;
    int lane = threadIdx.x & 31;
    int jL = jLarr[m], jR = jRarr[m];
    float qv = q[(size_t)m * 256 + h * 32 + lane] * ATTN_SCALE;
    int base = kvOff + h * 32 + lane;
    float d0 = 0.f, d1 = 0.f;
#pragma unroll
    for (int n = 0; n < 64; n++) {
        int w = (n < 32) ? jL : jR;
        int j = ((n & 31) << 7) + w;
        float p = KV[(size_t)j * 1024 + base] * qv;
        p += __shfl_xor_sync(0xffffffffu, p, 16);
        p += __shfl_xor_sync(0xffffffffu, p, 8);
        p += __shfl_xor_sync(0xffffffffu, p, 4);
        p += __shfl_xor_sync(0xffffffffu, p, 2);
        p += __shfl_xor_sync(0xffffffffu, p, 1);
        if (lane == (n & 31)) { if (n < 32) d0 = p; else d1 = p; }
    }
    float mx = fmaxf(d0, d1);
#pragma unroll
    for (int o = 16; o; o >>= 1) mx = fmaxf(mx, __shfl_xor_sync(0xffffffffu, mx, o));
    float e0 = expf(d0 - mx), e1 = expf(d1 - mx);
    float s = e0 + e1;
#pragma unroll
    for (int o = 16; o; o >>= 1) s += __shfl_xor_sync(0xffffffffu, s, o);
    float invs = 1.f / s;
    float p0 = e0 * invs, p1 = e1 * invs;
    float acc = 0.f;
#pragma unroll
    for (int n = 0; n < 64; n++) {
        float pn = __shfl_sync(0xffffffffu, (n < 32) ? p0 : p1, n & 31);
        int j = ((n & 31) << 7) + ((n < 32) ? jL : jR);
        acc = fmaf(pn, KV[(size_t)j * 1024 + base + 256], acc);
    }
    int col = h * 32 + lane;
    __nv_bfloat16 hi, lo;
    split_bf16(acc, hi, lo);
    size_t rb = (size_t)m * 768;
    acat[rb + col] = hi;
    acat[rb + 256 + col] = hi;
    acat[rb + 512 + col] = lo;
}

// =================== mma.sync bf16 GEMM: 128x64 tile, 3-stage, 1 sync/iter =========
// A: M x Krow rows; B: N x Krow rows (col-major B). 8 warps (4m x 2n), warp tile 32x32.
// EPI 0: Cf = acc (+bias)  EPI 1: Ccat = split(gelu(acc+bias)) [hi|hi|lo]  EPI 2: +bias+resid
#define ASTRIDE 80
#define STAGE_BYTES 15360  // A: 128*80=10240, B: 64*80=5120
#define NSTAGE 3
template <int EPI>
__global__ __launch_bounds__(256, 2) void mma_gemm(const __nv_bfloat16* __restrict__ A,
                                                   const __nv_bfloat16* __restrict__ B,
                                                   const float* __restrict__ bias,
                                                   const float* __restrict__ resid,
                                                   float* __restrict__ Cf,
                                                   __nv_bfloat16* __restrict__ Ccat,
                                                   int Krow, int N) {
    __shared__ __align__(16) char sm[NSTAGE * STAGE_BYTES];
    uint32_t smBase = smem_u32(sm);
    int tid = threadIdx.x;
    int wid = tid >> 5, lane = tid & 31;
    int wm = wid >> 1, wn = wid & 1;
    int m0 = blockIdx.y << 7, n0 = blockIdx.x << 6;
    int niter = Krow >> 5;

    float acc[2][4][4];
#pragma unroll
    for (int t = 0; t < 2; t++)
#pragma unroll
        for (int j = 0; j < 4; j++)
#pragma unroll
            for (int e = 0; e < 4; e++) acc[t][j][e] = 0.f;

    int arow = tid >> 2, ach = tid & 3;
    const __nv_bfloat16* gA0 = A + (size_t)m0 * Krow;
    const __nv_bfloat16* gB0 = B + (size_t)(n0 + arow) * Krow + (ach << 3);

    uint32_t aOff = (uint32_t)((wm * 32 + (lane & 15)) * ASTRIDE + (((lane >> 4) << 3) << 1));
    uint32_t bOff = (uint32_t)((wn * 32 + (lane & 7) + ((lane >> 4) << 3)) * ASTRIDE +
                               ((((lane >> 3) & 1) << 3) << 1));

    // prologue: stages 0,1
#pragma unroll
    for (int st = 0; st < NSTAGE - 1; st++) {
        uint32_t sA = smBase + st * STAGE_BYTES;
        int k0 = st << 5;
#pragma unroll
        for (int i = 0; i < 2; i++) {
            int u = tid + (i << 8);
            int row = u >> 2, ch = u & 3;
            cp16(sA + row * ASTRIDE + ch * 16, gA0 + (size_t)row * Krow + k0 + (ch << 3));
        }
        cp16(sA + 10240 + arow * ASTRIDE + ach * 16, gB0 + k0);
        cp_commit();
    }

    int stC = 0;              // compute stage
    int stP = NSTAGE - 1;     // prefetch stage
    for (int it = 0; it < niter; ++it) {
        cp_wait1();
        __syncthreads();
        // prefetch stage it+2 (into buffer used by compute it-1; all warps passed sync)
        if (it + NSTAGE - 1 < niter) {
            int k0 = (it + NSTAGE - 1) << 5;
            uint32_t sA = smBase + stP * STAGE_BYTES;
#pragma unroll
            for (int i = 0; i < 2; i++) {
                int u = tid + (i << 8);
                int row = u >> 2, ch = u & 3;
                cp16(sA + row * ASTRIDE + ch * 16, gA0 + (size_t)row * Krow + k0 + (ch << 3));
            }
            cp16(sA + 10240 + arow * ASTRIDE + ach * 16, gB0 + k0);
        }
        cp_commit();
        if (++stP == NSTAGE) stP = 0;

        uint32_t aBase = smBase + stC * STAGE_BYTES + aOff;
        uint32_t bBase = smBase + stC * STAGE_BYTES + 10240 + bOff;
        if (++stC == NSTAGE) stC = 0;
#pragma unroll
        for (int ks = 0; ks < 2; ks++) {
            uint32_t a[2][4], b[2][4];
            ldsm4(a[0], aBase + ks * 32);
            ldsm4(a[1], aBase + 16 * ASTRIDE + ks * 32);
            ldsm4(b[0], bBase + ks * 32);
            ldsm4(b[1], bBase + 16 * ASTRIDE + ks * 32);
#pragma unroll
            for (int t = 0; t < 2; t++) {
#pragma unroll
                for (int j = 0; j < 4; j++) {
                    uint32_t b0 = b[j >> 1][(j & 1) ? 2 : 0];
                    uint32_t b1 = b[j >> 1][(j & 1) ? 3 : 1];
                    mma16816(acc[t][j], a[t], b0, b1);
                }
            }
        }
    }

    // epilogue
#pragma unroll
    for (int t = 0; t < 2; t++) {
        int row0 = m0 + wm * 32 + t * 16 + (lane >> 2);
        int row1 = row0 + 8;
#pragma unroll
        for (int j = 0; j < 4; j++) {
            int col = n0 + wn * 32 + j * 8 + ((lane & 3) << 1);
            float v0 = acc[t][j][0], v1 = acc[t][j][1];
            float v2 = acc[t][j][2], v3 = acc[t][j][3];
            if (EPI != 0 || bias) {
                float b0 = bias[col], b1 = bias[col + 1];
                v0 += b0; v1 += b1; v2 += b0; v3 += b1;
            }
            if (EPI == 1) {
                v0 = 0.5f * v0 * (1.f + erff(v0 * 0.70710678118654752f));
                v1 = 0.5f * v1 * (1.f + erff(v1 * 0.70710678118654752f));
                v2 = 0.5f * v2 * (1.f + erff(v2 * 0.70710678118654752f));
                v3 = 0.5f * v3 * (1.f + erff(v3 * 0.70710678118654752f));
                __nv_bfloat16 h0, l0, h1, l1, h2, l2, h3, l3;
                split_bf16(v0, h0, l0); split_bf16(v1, h1, l1);
                split_bf16(v2, h2, l2); split_bf16(v3, h3, l3);
                size_t rb0 = (size_t)row0 * 3 * N + col;
                size_t rb1 = (size_t)row1 * 3 * N + col;
                *(__nv_bfloat162*)(Ccat + rb0) = __nv_bfloat162(h0, h1);
                *(__nv_bfloat162*)(Ccat + rb0 + N) = __nv_bfloat162(h0, h1);
                *(__nv_bfloat162*)(Ccat + rb0 + 2 * N) = __nv_bfloat162(l0, l1);
                *(__nv_bfloat162*)(Ccat + rb1) = __nv_bfloat162(h2, h3);
                *(__nv_bfloat162*)(Ccat + rb1 + N) = __nv_bfloat162(h2, h3);
                *(__nv_bfloat162*)(Ccat + rb1 + 2 * N) = __nv_bfloat162(l2, l3);
            } else {
                if (EPI == 2) {
                    float2 r0 = *(const float2*)(resid + (size_t)row0 * N + col);
                    float2 r1 = *(const float2*)(resid + (size_t)row1 * N + col);
                    v0 += r0.x; v1 += r0.y; v2 += r1.x; v3 += r1.y;
                }
                *(float2*)(Cf + (size_t)row0 * N + col) = make_float2(v0, v1);
                *(float2*)(Cf + (size_t)row1 * N + col) = make_float2(v2, v3);
            }
        }
    }
}

// =================== host launch ===================
extern "C" void kernel_launch(void* const* d_in, const int* in_sizes, int n_in,
                              void* d_out, int out_size) {
    (void)in_sizes; (void)n_in; (void)out_size;
    const float* grd2sat = (const float*)d_in[0];
    const float* grd_x   = (const float*)d_in[1];
    const float* u       = (const float*)d_in[2];
    const float* ln_q_w  = (const float*)d_in[3];
    const float* ln_q_b  = (const float*)d_in[4];
    const float* ln_k_w  = (const float*)d_in[5];
    const float* ln_k_b  = (const float*)d_in[6];
    const float* ln_v_w  = (const float*)d_in[7];
    const float* ln_v_b  = (const float*)d_in[8];
    const float* Wq      = (const float*)d_in[9];
    const float* Wk      = (const float*)d_in[10];
    const float* Wv      = (const float*)d_in[11];
    const float* Wproj   = (const float*)d_in[12];
    const float* bproj   = (const float*)d_in[13];
    const float* ln_pre_w  = (const float*)d_in[14];
    const float* ln_pre_b  = (const float*)d_in[15];
    const float* Wm1     = (const float*)d_in[16];
    const float* bm1     = (const float*)d_in[17];
    const float* Wm2     = (const float*)d_in[18];
    const float* bm2     = (const float*)d_in[19];
    const float* ln_post_w = (const float*)d_in[20];
    const float* ln_post_b = (const float*)d_in[21];
    float* out = (float*)d_out;

    __nv_bfloat16 *Xncat, *Wkvcat, *tcat, *acat, *z2cat, *hcat, *Wq2, *Wp2, *Wm1c, *Wm2c;
    float *bcat, *KV, *x, *q, *z1, *z2, *z3, *inv;
    int *jL, *jR;
    cudaGetSymbolAddress((void**)&Xncat, g_Xncat);
    cudaGetSymbolAddress((void**)&Wkvcat, g_Wkvcat);
    cudaGetSymbolAddress((void**)&bcat, g_bcat);
    cudaGetSymbolAddress((void**)&KV, g_KV);
    cudaGetSymbolAddress((void**)&x, g_x);
    cudaGetSymbolAddress((void**)&tcat, g_tcat);
    cudaGetSymbolAddress((void**)&q, g_q);
    cudaGetSymbolAddress((void**)&acat, g_acat);
    cudaGetSymbolAddress((void**)&z1, g_z1);
    cudaGetSymbolAddress((void**)&z2, g_z2);
    cudaGetSymbolAddress((void**)&z2cat, g_z2cat);
    cudaGetSymbolAddress((void**)&hcat, g_hcat);
    cudaGetSymbolAddress((void**)&z3, g_z3);
    cudaGetSymbolAddress((void**)&Wq2, g_Wq2);
    cudaGetSymbolAddress((void**)&Wp2, g_Wp2);
    cudaGetSymbolAddress((void**)&Wm1c, g_Wm1c);
    cudaGetSymbolAddress((void**)&Wm2c, g_Wm2c);
    cudaGetSymbolAddress((void**)&inv, g_inv);
    cudaGetSymbolAddress((void**)&jL, g_jL);
    cudaGetSymbolAddress((void**)&jR, g_jR);

    // ---- prep (once) ----
    idx_kernel<<<16, 256>>>(u, jL, jR);
    colnorm_kernel<<<128, 256>>>(grd_x, Xncat);
    fold_w_kernel<<<dim3(8, 8, 4), dim3(32, 8)>>>(Wk, Wv, ln_k_w, ln_v_w, Wkvcat);
    fold_b_kernel<<<128, 256>>>(Wk, Wv, ln_k_b, ln_v_b, bcat);

    WtJobs jobs;
    for (int i = 0; i < 2; i++) {
        jobs.j[i * 4 + 0] = {Wq + i * 65536, Wq2 + i * 256 * 768, 256, 256};
        jobs.j[i * 4 + 1] = {Wproj + i * 65536, Wp2 + i * 256 * 768, 256, 256};
        jobs.j[i * 4 + 2] = {Wm1 + i * 131072, Wm1c + i * 512 * 768, 256, 512};
        jobs.j[i * 4 + 3] = {Wm2 + i * 131072, Wm2c + i * 256 * 1536, 512, 256};
    }
    wtsplit_kernel<<<dim3(16, 16, 8), dim3(32, 8)>>>(jobs);

    // KV = Xn @ Wkv + bcat : (4096 x 1024)
    mma_gemm<0><<<dim3(16, 32), 256>>>(Xncat, Wkvcat, bcat, nullptr, KV, nullptr, 768, 1024);
    transpose_scale<<<dim3(128, 8), dim3(32, 8)>>>(grd2sat, x, 256, 4096, nullptr);

    for (int i = 0; i < 2; i++) {
        ln_kernel<<<512, 256>>>(x, ln_q_w + i * 256, ln_q_b + i * 256, nullptr, tcat);
        mma_gemm<0><<<dim3(4, 32), 256>>>(tcat, Wq2 + i * 256 * 768, nullptr, nullptr, q,
                                          nullptr, 768, 256);
        attn_kernel<<<4096, 256>>>(q, KV, jL, jR, i * 512, acat);
        mma_gemm<0><<<dim3(4, 32), 256>>>(acat, Wp2 + i * 256 * 768, bproj + i * 256,
                                          nullptr, z1, nullptr, 768, 256);
        ln_kernel<<<512, 256>>>(z1, ln_pre_w + i * 256, ln_pre_b + i * 256, z2, z2cat);
        mma_gemm<1><<<dim3(8, 32), 256>>>(z2cat, Wm1c + i * 512 * 768, bm1 + i * 512,
                                          nullptr, nullptr, hcat, 768, 512);
        mma_gemm<2><<<dim3(4, 32), 256>>>(hcat, Wm2c + i * 256 * 1536, bm2 + i * 256, z2,
                                          z3, nullptr, 1536, 256);
        ln_kernel<<<512, 256>>>(z3, ln_post_w + i * 256, ln_post_b + i * 256, x, nullptr);
    }

    invnorm_kernel<<<512, 256>>>(x, inv);
    transpose_scale<<<dim3(8, 128), dim3(32, 8)>>>(x, out, 4096, 256, inv);
}

// round 7
// speedup vs baseline: 2.3235x; 1.1685x over previous
#include <cuda_runtime.h>
#include <cuda_fp16.h>
#include <math.h>
#include <stdint.h>

#define ATTN_SCALE 0.17677669529663687f  // 32^-0.5

__device__ __forceinline__ uint32_t smem_u32(const void* p) {
    uint32_t a;
    asm("{ .reg .u64 t; cvta.to.shared.u64 t, %1; cvt.u32.u64 %0, t; }" : "=r"(a) : "l"(p));
    return a;
}
__device__ __forceinline__ void cp16(uint32_t s, const void* g) {
    asm volatile("cp.async.cg.shared.global [%0], [%1], 16;" :: "r"(s), "l"(g));
}
__device__ __forceinline__ void cp_commit() { asm volatile("cp.async.commit_group;"); }
__device__ __forceinline__ void cp_wait1() { asm volatile("cp.async.wait_group 1;"); }
__device__ __forceinline__ void ldsm4(uint32_t r[4], uint32_t addr) {
    asm volatile("ldmatrix.sync.aligned.m8n8.x4.shared.b16 {%0,%1,%2,%3}, [%4];"
                 : "=r"(r[0]), "=r"(r[1]), "=r"(r[2]), "=r"(r[3]) : "r"(addr));
}
__device__ __forceinline__ void mma16816(float c[4], const uint32_t a[4], uint32_t b0,
                                         uint32_t b1) {
    asm volatile(
        "mma.sync.aligned.m16n8k16.row.col.f32.f16.f16.f32 "
        "{%0,%1,%2,%3}, {%4,%5,%6,%7}, {%8,%9}, {%0,%1,%2,%3};"
        : "+f"(c[0]), "+f"(c[1]), "+f"(c[2]), "+f"(c[3])
        : "r"(a[0]), "r"(a[1]), "r"(a[2]), "r"(a[3]), "r"(b0), "r"(b1));
}
__device__ __forceinline__ void split_f16(float v, __half& hi, __half& lo) {
    hi = __float2half_rn(v);
    lo = __float2half_rn(v - __half2float(hi));
}

// =================== device scratch ===================
__device__ __half g_Xncat[4096 * 512];
__device__ __half g_Wkvcat[1024 * 512];
__device__ float g_bcat[1024];
__device__ float g_KV[4096 * 1024];
__device__ float g_x[4096 * 256];
__device__ __half g_tcat[4096 * 512];
__device__ float g_q[4096 * 256];
__device__ __half g_acat[4096 * 512];
__device__ float g_z1[4096 * 256];
__device__ float g_z2[4096 * 256];
__device__ __half g_z2cat[4096 * 512];
__device__ __half g_hcat[4096 * 1024];
__device__ float g_z3[4096 * 256];
__device__ __half g_Wq2[2 * 256 * 512];
__device__ __half g_Wp2[2 * 256 * 512];
__device__ __half g_Wm1c[2 * 512 * 512];
__device__ __half g_Wm2c[2 * 256 * 1024];
__device__ float g_inv[4096];
__device__ int g_jL[4096], g_jR[4096];

// =================== small prep kernels ===================
__global__ void idx_kernel(const float* __restrict__ u, int* __restrict__ jL,
                           int* __restrict__ jR) {
    int m = blockIdx.x * 256 + threadIdx.x;
    float uf = floorf(u[m]);
    jL[m] = (int)fminf(fmaxf(uf, 0.f), 127.f);
    jR[m] = (int)fminf(fmaxf(uf + 1.f, 0.f), 127.f);
}

// column-LN of grd_x (C=256 rows, 4096 cols) -> cat rows [h|l], coalesced
__global__ __launch_bounds__(256) void colnorm_kernel(const float* __restrict__ gx,
                                                      __half* __restrict__ cat) {
    __shared__ float tile[256][33];
    __shared__ float ps[8][32], pq[8][32];
    __shared__ float cmu[32], crs[32];
    int tx = threadIdx.x & 31, ty = threadIdx.x >> 5;
    int j0 = blockIdx.x * 32;
    float s = 0.f, q = 0.f;
#pragma unroll
    for (int t = 0; t < 32; t++) {
        int c = t * 8 + ty;
        float v = gx[(size_t)c * 4096 + j0 + tx];
        tile[c][tx] = v;
        s += v; q += v * v;
    }
    ps[ty][tx] = s; pq[ty][tx] = q;
    __syncthreads();
    if (ty == 0) {
        float ss = 0.f, qq = 0.f;
#pragma unroll
        for (int r = 0; r < 8; r++) { ss += ps[r][tx]; qq += pq[r][tx]; }
        float mu = ss * (1.f / 256.f);
        cmu[tx] = mu;
        crs[tx] = rsqrtf(qq * (1.f / 256.f) - mu * mu + 1e-5f);
    }
    __syncthreads();
    int lane = tx, w = ty;
#pragma unroll
    for (int r = 0; r < 4; r++) {
        int jj = w * 4 + r;
        float mu = cmu[jj], rs = crs[jj];
        size_t rb = (size_t)(j0 + jj) * 512 + lane * 8;
        __half h[8], l[8];
#pragma unroll
        for (int e = 0; e < 8; e++) {
            float v = (tile[lane * 8 + e][jj] - mu) * rs;
            split_f16(v, h[e], l[e]);
        }
        *(uint4*)(cat + rb) = *(uint4*)h;
        *(uint4*)(cat + rb + 256) = *(uint4*)l;
    }
}

// KV weights -> cat rows [h|h] (dup) with LN weight folded; tile transpose, coalesced
__global__ void fold_w_kernel(const float* __restrict__ Wk, const float* __restrict__ Wv,
                              const float* __restrict__ lnkw, const float* __restrict__ lnvw,
                              __half* __restrict__ cat) {
    __shared__ float t[32][33];
    int seg = blockIdx.z;          // 0..3 -> [k0,v0,k1,v1]
    int i = seg >> 1, isv = seg & 1;
    const float* W = (isv ? Wv : Wk) + i * 65536;
    const float* lw = (isv ? lnvw : lnkw) + i * 256;
    int c0 = blockIdx.x * 32, o0 = blockIdx.y * 32;
    int tx = threadIdx.x, ty = threadIdx.y;
#pragma unroll
    for (int s = 0; s < 4; s++) {
        int c = c0 + ty + s * 8;
        t[ty + s * 8][tx] = W[(size_t)c * 256 + o0 + tx] * lw[c];
    }
    __syncthreads();
#pragma unroll
    for (int s = 0; s < 4; s++) {
        int o = o0 + ty + s * 8;
        __half h = __float2half_rn(t[tx][ty + s * 8]);
        size_t rb = (size_t)(seg * 256 + o) * 512;
        cat[rb + c0 + tx] = h;
        cat[rb + 256 + c0 + tx] = h;
    }
}

// bcat[o] = sum_c ln_b[c] * W[c][o] ; warp per output
__global__ void fold_b_kernel(const float* __restrict__ Wk, const float* __restrict__ Wv,
                              const float* __restrict__ lnkb, const float* __restrict__ lnvb,
                              float* __restrict__ bcat) {
    int wid = threadIdx.x >> 5, lane = threadIdx.x & 31;
    int o = blockIdx.x * 8 + wid;  // grid 128
    int seg = o >> 8, oo = o & 255;
    int i = seg >> 1, isv = seg & 1;
    const float* W = (isv ? Wv : Wk) + i * 65536;
    const float* b = (isv ? lnvb : lnkb) + i * 256;
    float s = 0.f;
#pragma unroll
    for (int t = 0; t < 8; t++) {
        int c = lane + t * 32;
        s += b[c] * W[(size_t)c * 256 + oo];
    }
#pragma unroll
    for (int off = 16; off; off >>= 1) s += __shfl_xor_sync(0xffffffffu, s, off);
    if (lane == 0) bcat[o] = s;
}

// batched weight split-transpose: src (K x N fp32) -> dst (N x 2K fp16) [h|h] dup
struct WtJob { const float* src; __half* dst; int K; int N; };
struct WtJobs { WtJob j[8]; };
__global__ void wtsplit_kernel(WtJobs jobs) {
    __shared__ float t[32][33];
    WtJob jb = jobs.j[blockIdx.z];
    int k0 = blockIdx.x * 32, n0 = blockIdx.y * 32;
    if (k0 >= jb.K || n0 >= jb.N) return;
    int tx = threadIdx.x, ty = threadIdx.y;
#pragma unroll
    for (int s = 0; s < 4; s++) {
        int k = k0 + ty + s * 8;
        t[ty + s * 8][tx] = jb.src[(size_t)k * jb.N + n0 + tx];
    }
    __syncthreads();
    int K = jb.K;
#pragma unroll
    for (int s = 0; s < 4; s++) {
        int n = n0 + ty + s * 8;
        __half h = __float2half_rn(t[tx][ty + s * 8]);
        size_t rb = (size_t)n * 2 * K;
        jb.dst[rb + k0 + tx] = h;
        jb.dst[rb + K + k0 + tx] = h;
    }
}

// LayerNorm, warp per row; optional fp32 out and/or cat [h|l]
__global__ __launch_bounds__(256) void ln_kernel(const float* __restrict__ in,
                                                 const float* __restrict__ w,
                                                 const float* __restrict__ b,
                                                 float* __restrict__ outF,
                                                 __half* __restrict__ outCat) {
    int wid = threadIdx.x >> 5, lane = threadIdx.x & 31;
    int m = blockIdx.x * 8 + wid;
    const float4* ip = (const float4*)(in + (size_t)m * 256 + lane * 8);
    float4 v0 = ip[0], v1 = ip[1];
    float s = v0.x + v0.y + v0.z + v0.w + v1.x + v1.y + v1.z + v1.w;
#pragma unroll
    for (int o = 16; o; o >>= 1) s += __shfl_xor_sync(0xffffffffu, s, o);
    float mean = s * (1.f / 256.f);
    float x[8] = {v0.x - mean, v0.y - mean, v0.z - mean, v0.w - mean,
                  v1.x - mean, v1.y - mean, v1.z - mean, v1.w - mean};
    float q = 0.f;
#pragma unroll
    for (int e = 0; e < 8; e++) q = fmaf(x[e], x[e], q);
#pragma unroll
    for (int o = 16; o; o >>= 1) q += __shfl_xor_sync(0xffffffffu, q, o);
    float rstd = rsqrtf(q * (1.f / 256.f) + 1e-5f);
    float4 w0 = *(const float4*)(w + lane * 8), w1 = *(const float4*)(w + lane * 8 + 4);
    float4 b0 = *(const float4*)(b + lane * 8), b1 = *(const float4*)(b + lane * 8 + 4);
    float y[8];
    y[0] = x[0] * rstd * w0.x + b0.x; y[1] = x[1] * rstd * w0.y + b0.y;
    y[2] = x[2] * rstd * w0.z + b0.z; y[3] = x[3] * rstd * w0.w + b0.w;
    y[4] = x[4] * rstd * w1.x + b1.x; y[5] = x[5] * rstd * w1.y + b1.y;
    y[6] = x[6] * rstd * w1.z + b1.z; y[7] = x[7] * rstd * w1.w + b1.w;
    if (outF) {
        float4* op = (float4*)(outF + (size_t)m * 256 + lane * 8);
        op[0] = make_float4(y[0], y[1], y[2], y[3]);
        op[1] = make_float4(y[4], y[5], y[6], y[7]);
    }
    if (outCat) {
        __half h[8], l[8];
#pragma unroll
        for (int e = 0; e < 8; e++) split_f16(y[e], h[e], l[e]);
        size_t rb = (size_t)m * 512 + lane * 8;
        *(uint4*)(outCat + rb) = *(uint4*)h;
        *(uint4*)(outCat + rb + 256) = *(uint4*)l;
    }
}

__global__ __launch_bounds__(256) void invnorm_kernel(const float* __restrict__ x,
                                                      float* __restrict__ inv) {
    int wid = threadIdx.x >> 5, lane = threadIdx.x & 31;
    int m = blockIdx.x * 8 + wid;
    const float4* ip = (const float4*)(x + (size_t)m * 256 + lane * 8);
    float4 v0 = ip[0], v1 = ip[1];
    float q = v0.x * v0.x + v0.y * v0.y + v0.z * v0.z + v0.w * v0.w +
              v1.x * v1.x + v1.y * v1.y + v1.z * v1.z + v1.w * v1.w;
#pragma unroll
    for (int o = 16; o; o >>= 1) q += __shfl_xor_sync(0xffffffffu, q, o);
    if (lane == 0) inv[m] = 1.f / fmaxf(sqrtf(q), 1e-12f);
}

__global__ void transpose_scale(const float* __restrict__ in, float* __restrict__ out,
                                int R, int Cd, const float* __restrict__ scale) {
    __shared__ float t[32][33];
    int bx = blockIdx.x * 32, by = blockIdx.y * 32;
    int x = threadIdx.x, y0 = threadIdx.y;
    for (int yy = y0; yy < 32; yy += 8) {
        float s = scale ? scale[by + yy] : 1.f;
        t[yy][x] = in[(size_t)(by + yy) * Cd + bx + x] * s;
    }
    __syncthreads();
    for (int yy = y0; yy < 32; yy += 8)
        out[(size_t)(bx + yy) * R + by + x] = t[x][yy];
}

// =================== attention (coalesced loads, warp reduce) ======================
__global__ __launch_bounds__(256) void attn_kernel(const float* __restrict__ q,
                                                   const float* __restrict__ KV,
                                                   const int* __restrict__ jLarr,
                                                   const int* __restrict__ jRarr,
                                                   int kvOff,
                                                   __half* __restrict__ acat) {
    int m = blockIdx.x;
    int h = threadIdx.x >> 5;
    int lane = threadIdx.x & 31;
    int jL = jLarr[m], jR = jRarr[m];
    float qv = q[(size_t)m * 256 + h * 32 + lane] * ATTN_SCALE;
    int base = kvOff + h * 32 + lane;
    float d0 = 0.f, d1 = 0.f;
#pragma unroll
    for (int n = 0; n < 64; n++) {
        int w = (n < 32) ? jL : jR;
        int j = ((n & 31) << 7) + w;
        float p = KV[(size_t)j * 1024 + base] * qv;
        p += __shfl_xor_sync(0xffffffffu, p, 16);
        p += __shfl_xor_sync(0xffffffffu, p, 8);
        p += __shfl_xor_sync(0xffffffffu, p, 4);
        p += __shfl_xor_sync(0xffffffffu, p, 2);
        p += __shfl_xor_sync(0xffffffffu, p, 1);
        if (lane == (n & 31)) { if (n < 32) d0 = p; else d1 = p; }
    }
    float mx = fmaxf(d0, d1);
#pragma unroll
    for (int o = 16; o; o >>= 1) mx = fmaxf(mx, __shfl_xor_sync(0xffffffffu, mx, o));
    float e0 = expf(d0 - mx), e1 = expf(d1 - mx);
    float s = e0 + e1;
#pragma unroll
    for (int o = 16; o; o >>= 1) s += __shfl_xor_sync(0xffffffffu, s, o);
    float invs = 1.f / s;
    float p0 = e0 * invs, p1 = e1 * invs;
    float acc = 0.f;
#pragma unroll
    for (int n = 0; n < 64; n++) {
        float pn = __shfl_sync(0xffffffffu, (n < 32) ? p0 : p1, n & 31);
        int j = ((n & 31) << 7) + ((n < 32) ? jL : jR);
        acc = fmaf(pn, KV[(size_t)j * 1024 + base + 256], acc);
    }
    int col = h * 32 + lane;
    __half hi, lo;
    split_f16(acc, hi, lo);
    size_t rb = (size_t)m * 512;
    acat[rb + col] = hi;
    acat[rb + 256 + col] = lo;
}

// =================== mma.sync fp16 GEMM: 128x64 tile, 3-stage, 1 sync/iter =========
// A: M x Krow rows; B: N x Krow rows (col-major B). 8 warps (4m x 2n), warp tile 32x32.
// EPI 0: Cf = acc (+bias)  EPI 1: Ccat = split(gelu(acc+bias)) [h|l]  EPI 2: +bias+resid
#define ASTRIDE 80
#define STAGE_BYTES 15360  // A: 128*80=10240, B: 64*80=5120
#define NSTAGE 3
template <int EPI>
__global__ __launch_bounds__(256, 2) void mma_gemm(const __half* __restrict__ A,
                                                   const __half* __restrict__ B,
                                                   const float* __restrict__ bias,
                                                   const float* __restrict__ resid,
                                                   float* __restrict__ Cf,
                                                   __half* __restrict__ Ccat,
                                                   int Krow, int N) {
    __shared__ __align__(16) char sm[NSTAGE * STAGE_BYTES];
    uint32_t smBase = smem_u32(sm);
    int tid = threadIdx.x;
    int wid = tid >> 5, lane = tid & 31;
    int wm = wid >> 1, wn = wid & 1;
    int m0 = blockIdx.y << 7, n0 = blockIdx.x << 6;
    int niter = Krow >> 5;

    float acc[2][4][4];
#pragma unroll
    for (int t = 0; t < 2; t++)
#pragma unroll
        for (int j = 0; j < 4; j++)
#pragma unroll
            for (int e = 0; e < 4; e++) acc[t][j][e] = 0.f;

    int arow = tid >> 2, ach = tid & 3;
    const __half* gA0 = A + (size_t)m0 * Krow;
    const __half* gB0 = B + (size_t)(n0 + arow) * Krow + (ach << 3);

    uint32_t aOff = (uint32_t)((wm * 32 + (lane & 15)) * ASTRIDE + (((lane >> 4) << 3) << 1));
    uint32_t bOff = (uint32_t)((wn * 32 + (lane & 7) + ((lane >> 4) << 3)) * ASTRIDE +
                               ((((lane >> 3) & 1) << 3) << 1));

    // prologue: stages 0,1
#pragma unroll
    for (int st = 0; st < NSTAGE - 1; st++) {
        uint32_t sA = smBase + st * STAGE_BYTES;
        int k0 = st << 5;
#pragma unroll
        for (int i = 0; i < 2; i++) {
            int u = tid + (i << 8);
            int row = u >> 2, ch = u & 3;
            cp16(sA + row * ASTRIDE + ch * 16, gA0 + (size_t)row * Krow + k0 + (ch << 3));
        }
        cp16(sA + 10240 + arow * ASTRIDE + ach * 16, gB0 + k0);
        cp_commit();
    }

    int stC = 0;              // compute stage
    int stP = NSTAGE - 1;     // prefetch stage
    for (int it = 0; it < niter; ++it) {
        cp_wait1();
        __syncthreads();
        if (it + NSTAGE - 1 < niter) {
            int k0 = (it + NSTAGE - 1) << 5;
            uint32_t sA = smBase + stP * STAGE_BYTES;
#pragma unroll
            for (int i = 0; i < 2; i++) {
                int u = tid + (i << 8);
                int row = u >> 2, ch = u & 3;
                cp16(sA + row * ASTRIDE + ch * 16, gA0 + (size_t)row * Krow + k0 + (ch << 3));
            }
            cp16(sA + 10240 + arow * ASTRIDE + ach * 16, gB0 + k0);
        }
        cp_commit();
        if (++stP == NSTAGE) stP = 0;

        uint32_t aBase = smBase + stC * STAGE_BYTES + aOff;
        uint32_t bBase = smBase + stC * STAGE_BYTES + 10240 + bOff;
        if (++stC == NSTAGE) stC = 0;
#pragma unroll
        for (int ks = 0; ks < 2; ks++) {
            uint32_t a[2][4], b[2][4];
            ldsm4(a[0], aBase + ks * 32);
            ldsm4(a[1], aBase + 16 * ASTRIDE + ks * 32);
            ldsm4(b[0], bBase + ks * 32);
            ldsm4(b[1], bBase + 16 * ASTRIDE + ks * 32);
#pragma unroll
            for (int t = 0; t < 2; t++) {
#pragma unroll
                for (int j = 0; j < 4; j++) {
                    uint32_t b0 = b[j >> 1][(j & 1) ? 2 : 0];
                    uint32_t b1 = b[j >> 1][(j & 1) ? 3 : 1];
                    mma16816(acc[t][j], a[t], b0, b1);
                }
            }
        }
    }

    // epilogue
#pragma unroll
    for (int t = 0; t < 2; t++) {
        int row0 = m0 + wm * 32 + t * 16 + (lane >> 2);
        int row1 = row0 + 8;
#pragma unroll
        for (int j = 0; j < 4; j++) {
            int col = n0 + wn * 32 + j * 8 + ((lane & 3) << 1);
            float v0 = acc[t][j][0], v1 = acc[t][j][1];
            float v2 = acc[t][j][2], v3 = acc[t][j][3];
            if (EPI != 0 || bias) {
                float b0 = bias[col], b1 = bias[col + 1];
                v0 += b0; v1 += b1; v2 += b0; v3 += b1;
            }
            if (EPI == 1) {
                v0 = 0.5f * v0 * (1.f + erff(v0 * 0.70710678118654752f));
                v1 = 0.5f * v1 * (1.f + erff(v1 * 0.70710678118654752f));
                v2 = 0.5f * v2 * (1.f + erff(v2 * 0.70710678118654752f));
                v3 = 0.5f * v3 * (1.f + erff(v3 * 0.70710678118654752f));
                __half h0, l0, h1, l1, h2, l2, h3, l3;
                split_f16(v0, h0, l0); split_f16(v1, h1, l1);
                split_f16(v2, h2, l2); split_f16(v3, h3, l3);
                size_t rb0 = (size_t)row0 * 2 * N + col;
                size_t rb1 = (size_t)row1 * 2 * N + col;
                *(__half2*)(Ccat + rb0) = __halves2half2(h0, h1);
                *(__half2*)(Ccat + rb0 + N) = __halves2half2(l0, l1);
                *(__half2*)(Ccat + rb1) = __halves2half2(h2, h3);
                *(__half2*)(Ccat + rb1 + N) = __halves2half2(l2, l3);
            } else {
                if (EPI == 2) {
                    float2 r0 = *(const float2*)(resid + (size_t)row0 * N + col);
                    float2 r1 = *(const float2*)(resid + (size_t)row1 * N + col);
                    v0 += r0.x; v1 += r0.y; v2 += r1.x; v3 += r1.y;
                }
                *(float2*)(Cf + (size_t)row0 * N + col) = make_float2(v0, v1);
                *(float2*)(Cf + (size_t)row1 * N + col) = make_float2(v2, v3);
            }
        }
    }
}

// =================== host launch ===================
extern "C" void kernel_launch(void* const* d_in, const int* in_sizes, int n_in,
                              void* d_out, int out_size) {
    (void)in_sizes; (void)n_in; (void)out_size;
    const float* grd2sat = (const float*)d_in[0];
    const float* grd_x   = (const float*)d_in[1];
    const float* u       = (const float*)d_in[2];
    const float* ln_q_w  = (const float*)d_in[3];
    const float* ln_q_b  = (const float*)d_in[4];
    const float* ln_k_w  = (const float*)d_in[5];
    const float* ln_k_b  = (const float*)d_in[6];
    const float* ln_v_w  = (const float*)d_in[7];
    const float* ln_v_b  = (const float*)d_in[8];
    const float* Wq      = (const float*)d_in[9];
    const float* Wk      = (const float*)d_in[10];
    const float* Wv      = (const float*)d_in[11];
    const float* Wproj   = (const float*)d_in[12];
    const float* bproj   = (const float*)d_in[13];
    const float* ln_pre_w  = (const float*)d_in[14];
    const float* ln_pre_b  = (const float*)d_in[15];
    const float* Wm1     = (const float*)d_in[16];
    const float* bm1     = (const float*)d_in[17];
    const float* Wm2     = (const float*)d_in[18];
    const float* bm2     = (const float*)d_in[19];
    const float* ln_post_w = (const float*)d_in[20];
    const float* ln_post_b = (const float*)d_in[21];
    float* out = (float*)d_out;

    __half *Xncat, *Wkvcat, *tcat, *acat, *z2cat, *hcat, *Wq2, *Wp2, *Wm1c, *Wm2c;
    float *bcat, *KV, *x, *q, *z1, *z2, *z3, *inv;
    int *jL, *jR;
    cudaGetSymbolAddress((void**)&Xncat, g_Xncat);
    cudaGetSymbolAddress((void**)&Wkvcat, g_Wkvcat);
    cudaGetSymbolAddress((void**)&bcat, g_bcat);
    cudaGetSymbolAddress((void**)&KV, g_KV);
    cudaGetSymbolAddress((void**)&x, g_x);
    cudaGetSymbolAddress((void**)&tcat, g_tcat);
    cudaGetSymbolAddress((void**)&q, g_q);
    cudaGetSymbolAddress((void**)&acat, g_acat);
    cudaGetSymbolAddress((void**)&z1, g_z1);
    cudaGetSymbolAddress((void**)&z2, g_z2);
    cudaGetSymbolAddress((void**)&z2cat, g_z2cat);
    cudaGetSymbolAddress((void**)&hcat, g_hcat);
    cudaGetSymbolAddress((void**)&z3, g_z3);
    cudaGetSymbolAddress((void**)&Wq2, g_Wq2);
    cudaGetSymbolAddress((void**)&Wp2, g_Wp2);
    cudaGetSymbolAddress((void**)&Wm1c, g_Wm1c);
    cudaGetSymbolAddress((void**)&Wm2c, g_Wm2c);
    cudaGetSymbolAddress((void**)&inv, g_inv);
    cudaGetSymbolAddress((void**)&jL, g_jL);
    cudaGetSymbolAddress((void**)&jR, g_jR);

    // ---- prep (once) ----
    idx_kernel<<<16, 256>>>(u, jL, jR);
    colnorm_kernel<<<128, 256>>>(grd_x, Xncat);
    fold_w_kernel<<<dim3(8, 8, 4), dim3(32, 8)>>>(Wk, Wv, ln_k_w, ln_v_w, Wkvcat);
    fold_b_kernel<<<128, 256>>>(Wk, Wv, ln_k_b, ln_v_b, bcat);

    WtJobs jobs;
    for (int i = 0; i < 2; i++) {
        jobs.j[i * 4 + 0] = {Wq + i * 65536, Wq2 + i * 256 * 512, 256, 256};
        jobs.j[i * 4 + 1] = {Wproj + i * 65536, Wp2 + i * 256 * 512, 256, 256};
        jobs.j[i * 4 + 2] = {Wm1 + i * 131072, Wm1c + i * 512 * 512, 256, 512};
        jobs.j[i * 4 + 3] = {Wm2 + i * 131072, Wm2c + i * 256 * 1024, 512, 256};
    }
    wtsplit_kernel<<<dim3(16, 16, 8), dim3(32, 8)>>>(jobs);

    // KV = Xn @ Wkv + bcat : (4096 x 1024)
    mma_gemm<0><<<dim3(16, 32), 256>>>(Xncat, Wkvcat, bcat, nullptr, KV, nullptr, 512, 1024);
    transpose_scale<<<dim3(128, 8), dim3(32, 8)>>>(grd2sat, x, 256, 4096, nullptr);

    for (int i = 0; i < 2; i++) {
        ln_kernel<<<512, 256>>>(x, ln_q_w + i * 256, ln_q_b + i * 256, nullptr, tcat);
        mma_gemm<0><<<dim3(4, 32), 256>>>(tcat, Wq2 + i * 256 * 512, nullptr, nullptr, q,
                                          nullptr, 512, 256);
        attn_kernel<<<4096, 256>>>(q, KV, jL, jR, i * 512, acat);
        mma_gemm<0><<<dim3(4, 32), 256>>>(acat, Wp2 + i * 256 * 512, bproj + i * 256,
                                          nullptr, z1, nullptr, 512, 256);
        ln_kernel<<<512, 256>>>(z1, ln_pre_w + i * 256, ln_pre_b + i * 256, z2, z2cat);
        mma_gemm<1><<<dim3(8, 32), 256>>>(z2cat, Wm1c + i * 512 * 512, bm1 + i * 512,
                                          nullptr, nullptr, hcat, 512, 512);
        mma_gemm<2><<<dim3(4, 32), 256>>>(hcat, Wm2c + i * 256 * 1024, bm2 + i * 256, z2,
                                          z3, nullptr, 1024, 256);
        ln_kernel<<<512, 256>>>(z3, ln_post_w + i * 256, ln_post_b + i * 256, x, nullptr);
    }

    invnorm_kernel<<<512, 256>>>(x, inv);
    transpose_scale<<<dim3(8, 128), dim3(32, 8)>>>(x, out, 4096, 256, inv);
}

// round 8
// speedup vs baseline: 2.7051x; 1.1642x over previous
#include <cuda_runtime.h>
#include <cuda_fp16.h>
#include <math.h>
#include <stdint.h>

#define ATTN_SCALE 0.17677669529663687f  // 32^-0.5

__device__ __forceinline__ uint32_t smem_u32(const void* p) {
    uint32_t a;
    asm("{ .reg .u64 t; cvta.to.shared.u64 t, %1; cvt.u32.u64 %0, t; }" : "=r"(a) : "l"(p));
    return a;
}
__device__ __forceinline__ void cp16(uint32_t s, const void* g) {
    asm volatile("cp.async.cg.shared.global [%0], [%1], 16;" :: "r"(s), "l"(g));
}
__device__ __forceinline__ void cp_commit() { asm volatile("cp.async.commit_group;"); }
__device__ __forceinline__ void cp_wait1() { asm volatile("cp.async.wait_group 1;"); }
__device__ __forceinline__ void ldsm4(uint32_t r[4], uint32_t addr) {
    asm volatile("ldmatrix.sync.aligned.m8n8.x4.shared.b16 {%0,%1,%2,%3}, [%4];"
                 : "=r"(r[0]), "=r"(r[1]), "=r"(r[2]), "=r"(r[3]) : "r"(addr));
}
__device__ __forceinline__ void mma16816(float c[4], const uint32_t a[4], uint32_t b0,
                                         uint32_t b1) {
    asm volatile(
        "mma.sync.aligned.m16n8k16.row.col.f32.f16.f16.f32 "
        "{%0,%1,%2,%3}, {%4,%5,%6,%7}, {%8,%9}, {%0,%1,%2,%3};"
        : "+f"(c[0]), "+f"(c[1]), "+f"(c[2]), "+f"(c[3])
        : "r"(a[0]), "r"(a[1]), "r"(a[2]), "r"(a[3]), "r"(b0), "r"(b1));
}

// =================== device scratch ===================
__device__ __half g_Xn[4096 * 256];
__device__ __half g_Wkv[1024 * 256];
__device__ float g_bcat[1024];
__device__ float g_KV[4096 * 1024];
__device__ float g_x[4096 * 256];
__device__ __half g_t16[4096 * 256];
__device__ float g_q[4096 * 256];
__device__ __half g_a16[4096 * 256];
__device__ float g_z1[4096 * 256];
__device__ float g_z2[4096 * 256];
__device__ __half g_z216[4096 * 256];
__device__ __half g_h16[4096 * 512];
__device__ float g_z3[4096 * 256];
__device__ __half g_Wq2[2 * 256 * 256];
__device__ __half g_Wp2[2 * 256 * 256];
__device__ __half g_Wm1c[2 * 512 * 256];
__device__ __half g_Wm2c[2 * 256 * 512];
__device__ float g_inv[4096];
__device__ int g_jL[4096], g_jR[4096];

// =================== small prep kernels ===================
__global__ void idx_kernel(const float* __restrict__ u, int* __restrict__ jL,
                           int* __restrict__ jR) {
    int m = blockIdx.x * 256 + threadIdx.x;
    float uf = floorf(u[m]);
    jL[m] = (int)fminf(fmaxf(uf, 0.f), 127.f);
    jR[m] = (int)fminf(fmaxf(uf + 1.f, 0.f), 127.f);
}

// column-LN of grd_x (C=256 rows, 4096 cols) -> fp16 rows, coalesced
__global__ __launch_bounds__(256) void colnorm_kernel(const float* __restrict__ gx,
                                                      __half* __restrict__ cat) {
    __shared__ float tile[256][33];
    __shared__ float ps[8][32], pq[8][32];
    __shared__ float cmu[32], crs[32];
    int tx = threadIdx.x & 31, ty = threadIdx.x >> 5;
    int j0 = blockIdx.x * 32;
    float s = 0.f, q = 0.f;
#pragma unroll
    for (int t = 0; t < 32; t++) {
        int c = t * 8 + ty;
        float v = gx[(size_t)c * 4096 + j0 + tx];
        tile[c][tx] = v;
        s += v; q += v * v;
    }
    ps[ty][tx] = s; pq[ty][tx] = q;
    __syncthreads();
    if (ty == 0) {
        float ss = 0.f, qq = 0.f;
#pragma unroll
        for (int r = 0; r < 8; r++) { ss += ps[r][tx]; qq += pq[r][tx]; }
        float mu = ss * (1.f / 256.f);
        cmu[tx] = mu;
        crs[tx] = rsqrtf(qq * (1.f / 256.f) - mu * mu + 1e-5f);
    }
    __syncthreads();
    int lane = tx, w = ty;
#pragma unroll
    for (int r = 0; r < 4; r++) {
        int jj = w * 4 + r;
        float mu = cmu[jj], rs = crs[jj];
        size_t rb = (size_t)(j0 + jj) * 256 + lane * 8;
        __half h[8];
#pragma unroll
        for (int e = 0; e < 8; e++)
            h[e] = __float2half_rn((tile[lane * 8 + e][jj] - mu) * rs);
        *(uint4*)(cat + rb) = *(uint4*)h;
    }
}

// KV weights -> fp16 rows with LN weight folded; tile transpose, coalesced
__global__ void fold_w_kernel(const float* __restrict__ Wk, const float* __restrict__ Wv,
                              const float* __restrict__ lnkw, const float* __restrict__ lnvw,
                              __half* __restrict__ cat) {
    __shared__ float t[32][33];
    int seg = blockIdx.z;          // 0..3 -> [k0,v0,k1,v1]
    int i = seg >> 1, isv = seg & 1;
    const float* W = (isv ? Wv : Wk) + i * 65536;
    const float* lw = (isv ? lnvw : lnkw) + i * 256;
    int c0 = blockIdx.x * 32, o0 = blockIdx.y * 32;
    int tx = threadIdx.x, ty = threadIdx.y;
#pragma unroll
    for (int s = 0; s < 4; s++) {
        int c = c0 + ty + s * 8;
        t[ty + s * 8][tx] = W[(size_t)c * 256 + o0 + tx] * lw[c];
    }
    __syncthreads();
#pragma unroll
    for (int s = 0; s < 4; s++) {
        int o = o0 + ty + s * 8;
        size_t rb = (size_t)(seg * 256 + o) * 256;
        cat[rb + c0 + tx] = __float2half_rn(t[tx][ty + s * 8]);
    }
}

// bcat[o] = sum_c ln_b[c] * W[c][o] ; warp per output
__global__ void fold_b_kernel(const float* __restrict__ Wk, const float* __restrict__ Wv,
                              const float* __restrict__ lnkb, const float* __restrict__ lnvb,
                              float* __restrict__ bcat) {
    int wid = threadIdx.x >> 5, lane = threadIdx.x & 31;
    int o = blockIdx.x * 8 + wid;  // grid 128
    int seg = o >> 8, oo = o & 255;
    int i = seg >> 1, isv = seg & 1;
    const float* W = (isv ? Wv : Wk) + i * 65536;
    const float* b = (isv ? lnvb : lnkb) + i * 256;
    float s = 0.f;
#pragma unroll
    for (int t = 0; t < 8; t++) {
        int c = lane + t * 32;
        s += b[c] * W[(size_t)c * 256 + oo];
    }
#pragma unroll
    for (int off = 16; off; off >>= 1) s += __shfl_xor_sync(0xffffffffu, s, off);
    if (lane == 0) bcat[o] = s;
}

// batched weight transpose->fp16: src (K x N fp32) -> dst (N x K fp16)
struct WtJob { const float* src; __half* dst; int K; int N; };
struct WtJobs { WtJob j[8]; };
__global__ void wtsplit_kernel(WtJobs jobs) {
    __shared__ float t[32][33];
    WtJob jb = jobs.j[blockIdx.z];
    int k0 = blockIdx.x * 32, n0 = blockIdx.y * 32;
    if (k0 >= jb.K || n0 >= jb.N) return;
    int tx = threadIdx.x, ty = threadIdx.y;
#pragma unroll
    for (int s = 0; s < 4; s++) {
        int k = k0 + ty + s * 8;
        t[ty + s * 8][tx] = jb.src[(size_t)k * jb.N + n0 + tx];
    }
    __syncthreads();
    int K = jb.K;
#pragma unroll
    for (int s = 0; s < 4; s++) {
        int n = n0 + ty + s * 8;
        jb.dst[(size_t)n * K + k0 + tx] = __float2half_rn(t[tx][ty + s * 8]);
    }
}

// LayerNorm, warp per row; optional fp32 out and/or fp16 out
__global__ __launch_bounds__(256) void ln_kernel(const float* __restrict__ in,
                                                 const float* __restrict__ w,
                                                 const float* __restrict__ b,
                                                 float* __restrict__ outF,
                                                 __half* __restrict__ outH) {
    int wid = threadIdx.x >> 5, lane = threadIdx.x & 31;
    int m = blockIdx.x * 8 + wid;
    const float4* ip = (const float4*)(in + (size_t)m * 256 + lane * 8);
    float4 v0 = ip[0], v1 = ip[1];
    float s = v0.x + v0.y + v0.z + v0.w + v1.x + v1.y + v1.z + v1.w;
#pragma unroll
    for (int o = 16; o; o >>= 1) s += __shfl_xor_sync(0xffffffffu, s, o);
    float mean = s * (1.f / 256.f);
    float x[8] = {v0.x - mean, v0.y - mean, v0.z - mean, v0.w - mean,
                  v1.x - mean, v1.y - mean, v1.z - mean, v1.w - mean};
    float q = 0.f;
#pragma unroll
    for (int e = 0; e < 8; e++) q = fmaf(x[e], x[e], q);
#pragma unroll
    for (int o = 16; o; o >>= 1) q += __shfl_xor_sync(0xffffffffu, q, o);
    float rstd = rsqrtf(q * (1.f / 256.f) + 1e-5f);
    float4 w0 = *(const float4*)(w + lane * 8), w1 = *(const float4*)(w + lane * 8 + 4);
    float4 b0 = *(const float4*)(b + lane * 8), b1 = *(const float4*)(b + lane * 8 + 4);
    float y[8];
    y[0] = x[0] * rstd * w0.x + b0.x; y[1] = x[1] * rstd * w0.y + b0.y;
    y[2] = x[2] * rstd * w0.z + b0.z; y[3] = x[3] * rstd * w0.w + b0.w;
    y[4] = x[4] * rstd * w1.x + b1.x; y[5] = x[5] * rstd * w1.y + b1.y;
    y[6] = x[6] * rstd * w1.z + b1.z; y[7] = x[7] * rstd * w1.w + b1.w;
    if (outF) {
        float4* op = (float4*)(outF + (size_t)m * 256 + lane * 8);
        op[0] = make_float4(y[0], y[1], y[2], y[3]);
        op[1] = make_float4(y[4], y[5], y[6], y[7]);
    }
    if (outH) {
        __half h[8];
#pragma unroll
        for (int e = 0; e < 8; e++) h[e] = __float2half_rn(y[e]);
        *(uint4*)(outH + (size_t)m * 256 + lane * 8) = *(uint4*)h;
    }
}

__global__ __launch_bounds__(256) void invnorm_kernel(const float* __restrict__ x,
                                                      float* __restrict__ inv) {
    int wid = threadIdx.x >> 5, lane = threadIdx.x & 31;
    int m = blockIdx.x * 8 + wid;
    const float4* ip = (const float4*)(x + (size_t)m * 256 + lane * 8);
    float4 v0 = ip[0], v1 = ip[1];
    float q = v0.x * v0.x + v0.y * v0.y + v0.z * v0.z + v0.w * v0.w +
              v1.x * v1.x + v1.y * v1.y + v1.z * v1.z + v1.w * v1.w;
#pragma unroll
    for (int o = 16; o; o >>= 1) q += __shfl_xor_sync(0xffffffffu, q, o);
    if (lane == 0) inv[m] = 1.f / fmaxf(sqrtf(q), 1e-12f);
}

__global__ void transpose_scale(const float* __restrict__ in, float* __restrict__ out,
                                int R, int Cd, const float* __restrict__ scale) {
    __shared__ float t[32][33];
    int bx = blockIdx.x * 32, by = blockIdx.y * 32;
    int x = threadIdx.x, y0 = threadIdx.y;
    for (int yy = y0; yy < 32; yy += 8) {
        float s = scale ? scale[by + yy] : 1.f;
        t[yy][x] = in[(size_t)(by + yy) * Cd + bx + x] * s;
    }
    __syncthreads();
    for (int yy = y0; yy < 32; yy += 8)
        out[(size_t)(bx + yy) * R + by + x] = t[x][yy];
}

// =================== attention (coalesced loads, warp reduce) ======================
__global__ __launch_bounds__(256) void attn_kernel(const float* __restrict__ q,
                                                   const float* __restrict__ KV,
                                                   const int* __restrict__ jLarr,
                                                   const int* __restrict__ jRarr,
                                                   int kvOff,
                                                   __half* __restrict__ a16) {
    int m = blockIdx.x;
    int h = threadIdx.x >> 5;
    int lane = threadIdx.x & 31;
    int jL = jLarr[m], jR = jRarr[m];
    float qv = q[(size_t)m * 256 + h * 32 + lane] * ATTN_SCALE;
    int base = kvOff + h * 32 + lane;
    float d0 = 0.f, d1 = 0.f;
#pragma unroll
    for (int n = 0; n < 64; n++) {
        int w = (n < 32) ? jL : jR;
        int j = ((n & 31) << 7) + w;
        float p = KV[(size_t)j * 1024 + base] * qv;
        p += __shfl_xor_sync(0xffffffffu, p, 16);
        p += __shfl_xor_sync(0xffffffffu, p, 8);
        p += __shfl_xor_sync(0xffffffffu, p, 4);
        p += __shfl_xor_sync(0xffffffffu, p, 2);
        p += __shfl_xor_sync(0xffffffffu, p, 1);
        if (lane == (n & 31)) { if (n < 32) d0 = p; else d1 = p; }
    }
    float mx = fmaxf(d0, d1);
#pragma unroll
    for (int o = 16; o; o >>= 1) mx = fmaxf(mx, __shfl_xor_sync(0xffffffffu, mx, o));
    float e0 = expf(d0 - mx), e1 = expf(d1 - mx);
    float s = e0 + e1;
#pragma unroll
    for (int o = 16; o; o >>= 1) s += __shfl_xor_sync(0xffffffffu, s, o);
    float invs = 1.f / s;
    float p0 = e0 * invs, p1 = e1 * invs;
    float acc = 0.f;
#pragma unroll
    for (int n = 0; n < 64; n++) {
        float pn = __shfl_sync(0xffffffffu, (n < 32) ? p0 : p1, n & 31);
        int j = ((n & 31) << 7) + ((n < 32) ? jL : jR);
        acc = fmaf(pn, KV[(size_t)j * 1024 + base + 256], acc);
    }
    a16[(size_t)m * 256 + h * 32 + lane] = __float2half_rn(acc);
}

// =================== mma.sync fp16 GEMM: 128x64 tile, 3-stage, 1 sync/iter =========
// A: M x Krow rows; B: N x Krow rows (col-major B). 8 warps (4m x 2n), warp tile 32x32.
// EPI 0: Cf = acc (+bias)  EPI 1: Ch = f16(gelu(acc+bias))  EPI 2: Cf = acc+bias+resid
#define ASTRIDE 80
#define STAGE_BYTES 15360  // A: 128*80=10240, B: 64*80=5120
#define NSTAGE 3
template <int EPI>
__global__ __launch_bounds__(256, 2) void mma_gemm(const __half* __restrict__ A,
                                                   const __half* __restrict__ B,
                                                   const float* __restrict__ bias,
                                                   const float* __restrict__ resid,
                                                   float* __restrict__ Cf,
                                                   __half* __restrict__ Ch,
                                                   int Krow, int N) {
    __shared__ __align__(16) char sm[NSTAGE * STAGE_BYTES];
    uint32_t smBase = smem_u32(sm);
    int tid = threadIdx.x;
    int wid = tid >> 5, lane = tid & 31;
    int wm = wid >> 1, wn = wid & 1;
    int m0 = blockIdx.y << 7, n0 = blockIdx.x << 6;
    int niter = Krow >> 5;

    float acc[2][4][4];
#pragma unroll
    for (int t = 0; t < 2; t++)
#pragma unroll
        for (int j = 0; j < 4; j++)
#pragma unroll
            for (int e = 0; e < 4; e++) acc[t][j][e] = 0.f;

    int arow = tid >> 2, ach = tid & 3;
    const __half* gA0 = A + (size_t)m0 * Krow;
    const __half* gB0 = B + (size_t)(n0 + arow) * Krow + (ach << 3);

    uint32_t aOff = (uint32_t)((wm * 32 + (lane & 15)) * ASTRIDE + (((lane >> 4) << 3) << 1));
    uint32_t bOff = (uint32_t)((wn * 32 + (lane & 7) + ((lane >> 4) << 3)) * ASTRIDE +
                               ((((lane >> 3) & 1) << 3) << 1));

    // prologue: stages 0,1
#pragma unroll
    for (int st = 0; st < NSTAGE - 1; st++) {
        uint32_t sA = smBase + st * STAGE_BYTES;
        int k0 = st << 5;
#pragma unroll
        for (int i = 0; i < 2; i++) {
            int u = tid + (i << 8);
            int row = u >> 2, ch = u & 3;
            cp16(sA + row * ASTRIDE + ch * 16, gA0 + (size_t)row * Krow + k0 + (ch << 3));
        }
        cp16(sA + 10240 + arow * ASTRIDE + ach * 16, gB0 + k0);
        cp_commit();
    }

    int stC = 0;              // compute stage
    int stP = NSTAGE - 1;     // prefetch stage
    for (int it = 0; it < niter; ++it) {
        cp_wait1();
        __syncthreads();
        if (it + NSTAGE - 1 < niter) {
            int k0 = (it + NSTAGE - 1) << 5;
            uint32_t sA = smBase + stP * STAGE_BYTES;
#pragma unroll
            for (int i = 0; i < 2; i++) {
                int u = tid + (i << 8);
                int row = u >> 2, ch = u & 3;
                cp16(sA + row * ASTRIDE + ch * 16, gA0 + (size_t)row * Krow + k0 + (ch << 3));
            }
            cp16(sA + 10240 + arow * ASTRIDE + ach * 16, gB0 + k0);
        }
        cp_commit();
        if (++stP == NSTAGE) stP = 0;

        uint32_t aBase = smBase + stC * STAGE_BYTES + aOff;
        uint32_t bBase = smBase + stC * STAGE_BYTES + 10240 + bOff;
        if (++stC == NSTAGE) stC = 0;
#pragma unroll
        for (int ks = 0; ks < 2; ks++) {
            uint32_t a[2][4], b[2][4];
            ldsm4(a[0], aBase + ks * 32);
            ldsm4(a[1], aBase + 16 * ASTRIDE + ks * 32);
            ldsm4(b[0], bBase + ks * 32);
            ldsm4(b[1], bBase + 16 * ASTRIDE + ks * 32);
#pragma unroll
            for (int t = 0; t < 2; t++) {
#pragma unroll
                for (int j = 0; j < 4; j++) {
                    uint32_t b0 = b[j >> 1][(j & 1) ? 2 : 0];
                    uint32_t b1 = b[j >> 1][(j & 1) ? 3 : 1];
                    mma16816(acc[t][j], a[t], b0, b1);
                }
            }
        }
    }

    // epilogue
#pragma unroll
    for (int t = 0; t < 2; t++) {
        int row0 = m0 + wm * 32 + t * 16 + (lane >> 2);
        int row1 = row0 + 8;
#pragma unroll
        for (int j = 0; j < 4; j++) {
            int col = n0 + wn * 32 + j * 8 + ((lane & 3) << 1);
            float v0 = acc[t][j][0], v1 = acc[t][j][1];
            float v2 = acc[t][j][2], v3 = acc[t][j][3];
            if (EPI != 0 || bias) {
                float b0 = bias[col], b1 = bias[col + 1];
                v0 += b0; v1 += b1; v2 += b0; v3 += b1;
            }
            if (EPI == 1) {
                v0 = 0.5f * v0 * (1.f + erff(v0 * 0.70710678118654752f));
                v1 = 0.5f * v1 * (1.f + erff(v1 * 0.70710678118654752f));
                v2 = 0.5f * v2 * (1.f + erff(v2 * 0.70710678118654752f));
                v3 = 0.5f * v3 * (1.f + erff(v3 * 0.70710678118654752f));
                *(__half2*)(Ch + (size_t)row0 * N + col) =
                    __halves2half2(__float2half_rn(v0), __float2half_rn(v1));
                *(__half2*)(Ch + (size_t)row1 * N + col) =
                    __halves2half2(__float2half_rn(v2), __float2half_rn(v3));
            } else {
                if (EPI == 2) {
                    float2 r0 = *(const float2*)(resid + (size_t)row0 * N + col);
                    float2 r1 = *(const float2*)(resid + (size_t)row1 * N + col);
                    v0 += r0.x; v1 += r0.y; v2 += r1.x; v3 += r1.y;
                }
                *(float2*)(Cf + (size_t)row0 * N + col) = make_float2(v0, v1);
                *(float2*)(Cf + (size_t)row1 * N + col) = make_float2(v2, v3);
            }
        }
    }
}

// =================== host launch ===================
extern "C" void kernel_launch(void* const* d_in, const int* in_sizes, int n_in,
                              void* d_out, int out_size) {
    (void)in_sizes; (void)n_in; (void)out_size;
    const float* grd2sat = (const float*)d_in[0];
    const float* grd_x   = (const float*)d_in[1];
    const float* u       = (const float*)d_in[2];
    const float* ln_q_w  = (const float*)d_in[3];
    const float* ln_q_b  = (const float*)d_in[4];
    const float* ln_k_w  = (const float*)d_in[5];
    const float* ln_k_b  = (const float*)d_in[6];
    const float* ln_v_w  = (const float*)d_in[7];
    const float* ln_v_b  = (const float*)d_in[8];
    const float* Wq      = (const float*)d_in[9];
    const float* Wk      = (const float*)d_in[10];
    const float* Wv      = (const float*)d_in[11];
    const float* Wproj   = (const float*)d_in[12];
    const float* bproj   = (const float*)d_in[13];
    const float* ln_pre_w  = (const float*)d_in[14];
    const float* ln_pre_b  = (const float*)d_in[15];
    const float* Wm1     = (const float*)d_in[16];
    const float* bm1     = (const float*)d_in[17];
    const float* Wm2     = (const float*)d_in[18];
    const float* bm2     = (const float*)d_in[19];
    const float* ln_post_w = (const float*)d_in[20];
    const float* ln_post_b = (const float*)d_in[21];
    float* out = (float*)d_out;

    __half *Xn, *Wkv, *t16, *a16, *z216, *h16, *Wq2, *Wp2, *Wm1c, *Wm2c;
    float *bcat, *KV, *x, *q, *z1, *z2, *z3, *inv;
    int *jL, *jR;
    cudaGetSymbolAddress((void**)&Xn, g_Xn);
    cudaGetSymbolAddress((void**)&Wkv, g_Wkv);
    cudaGetSymbolAddress((void**)&bcat, g_bcat);
    cudaGetSymbolAddress((void**)&KV, g_KV);
    cudaGetSymbolAddress((void**)&x, g_x);
    cudaGetSymbolAddress((void**)&t16, g_t16);
    cudaGetSymbolAddress((void**)&q, g_q);
    cudaGetSymbolAddress((void**)&a16, g_a16);
    cudaGetSymbolAddress((void**)&z1, g_z1);
    cudaGetSymbolAddress((void**)&z2, g_z2);
    cudaGetSymbolAddress((void**)&z216, g_z216);
    cudaGetSymbolAddress((void**)&h16, g_h16);
    cudaGetSymbolAddress((void**)&z3, g_z3);
    cudaGetSymbolAddress((void**)&Wq2, g_Wq2);
    cudaGetSymbolAddress((void**)&Wp2, g_Wp2);
    cudaGetSymbolAddress((void**)&Wm1c, g_Wm1c);
    cudaGetSymbolAddress((void**)&Wm2c, g_Wm2c);
    cudaGetSymbolAddress((void**)&inv, g_inv);
    cudaGetSymbolAddress((void**)&jL, g_jL);
    cudaGetSymbolAddress((void**)&jR, g_jR);

    // ---- prep (once) ----
    idx_kernel<<<16, 256>>>(u, jL, jR);
    colnorm_kernel<<<128, 256>>>(grd_x, Xn);
    fold_w_kernel<<<dim3(8, 8, 4), dim3(32, 8)>>>(Wk, Wv, ln_k_w, ln_v_w, Wkv);
    fold_b_kernel<<<128, 256>>>(Wk, Wv, ln_k_b, ln_v_b, bcat);

    WtJobs jobs;
    for (int i = 0; i < 2; i++) {
        jobs.j[i * 4 + 0] = {Wq + i * 65536, Wq2 + i * 256 * 256, 256, 256};
        jobs.j[i * 4 + 1] = {Wproj + i * 65536, Wp2 + i * 256 * 256, 256, 256};
        jobs.j[i * 4 + 2] = {Wm1 + i * 131072, Wm1c + i * 512 * 256, 256, 512};
        jobs.j[i * 4 + 3] = {Wm2 + i * 131072, Wm2c + i * 256 * 512, 512, 256};
    }
    wtsplit_kernel<<<dim3(16, 16, 8), dim3(32, 8)>>>(jobs);

    // KV = Xn @ Wkv + bcat : (4096 x 1024)
    mma_gemm<0><<<dim3(16, 32), 256>>>(Xn, Wkv, bcat, nullptr, KV, nullptr, 256, 1024);
    transpose_scale<<<dim3(128, 8), dim3(32, 8)>>>(grd2sat, x, 256, 4096, nullptr);

    for (int i = 0; i < 2; i++) {
        ln_kernel<<<512, 256>>>(x, ln_q_w + i * 256, ln_q_b + i * 256, nullptr, t16);
        mma_gemm<0><<<dim3(4, 32), 256>>>(t16, Wq2 + i * 256 * 256, nullptr, nullptr, q,
                                          nullptr, 256, 256);
        attn_kernel<<<4096, 256>>>(q, KV, jL, jR, i * 512, a16);
        mma_gemm<0><<<dim3(4, 32), 256>>>(a16, Wp2 + i * 256 * 256, bproj + i * 256,
                                          nullptr, z1, nullptr, 256, 256);
        ln_kernel<<<512, 256>>>(z1, ln_pre_w + i * 256, ln_pre_b + i * 256, z2, z216);
        mma_gemm<1><<<dim3(8, 32), 256>>>(z216, Wm1c + i * 512 * 256, bm1 + i * 512,
                                          nullptr, nullptr, h16, 256, 512);
        mma_gemm<2><<<dim3(4, 32), 256>>>(h16, Wm2c + i * 256 * 512, bm2 + i * 256, z2,
                                          z3, nullptr, 512, 256);
        ln_kernel<<<512, 256>>>(z3, ln_post_w + i * 256, ln_post_b + i * 256, x, nullptr);
    }

    invnorm_kernel<<<512, 256>>>(x, inv);
    transpose_scale<<<dim3(8, 128), dim3(32, 8)>>>(x, out, 4096, 256, inv);
}